// round 13
// baseline (speedup 1.0000x reference)
#include <cuda_runtime.h>
#include <math.h>

#define FULLMASK 0xffffffffu
typedef unsigned long long u64;

// ---------------- packed f32x2 helpers ----------------
__device__ __forceinline__ u64 pack2(float lo, float hi) {
    u64 r; asm("mov.b64 %0, {%1, %2};" : "=l"(r) : "f"(lo), "f"(hi)); return r;
}
__device__ __forceinline__ u64 splat2(float a) {
    u64 r; asm("mov.b64 %0, {%1, %1};" : "=l"(r) : "f"(a)); return r;
}
__device__ __forceinline__ void unpack2(u64 a, float& x, float& y) {
    asm("mov.b64 {%0, %1}, %2;" : "=f"(x), "=f"(y) : "l"(a));
}
__device__ __forceinline__ u64 fma2(u64 a, u64 b, u64 c) {
    u64 r; asm("fma.rn.f32x2 %0, %1, %2, %3;" : "=l"(r) : "l"(a), "l"(b), "l"(c)); return r;
}
__device__ __forceinline__ u64 add2(u64 a, u64 b) {
    u64 r; asm("add.rn.f32x2 %0, %1, %2;" : "=l"(r) : "l"(a), "l"(b)); return r;
}
__device__ __forceinline__ u64 mul2(u64 a, u64 b) {
    u64 r; asm("mul.rn.f32x2 %0, %1, %2;" : "=l"(r) : "l"(a), "l"(b)); return r;
}
__device__ __forceinline__ u64 abs2(u64 a) {
    u64 r; asm("and.b64 %0, %1, 0x7FFFFFFF7FFFFFFF;" : "=l"(r) : "l"(a)); return r;
}
__device__ __forceinline__ u64 neg2(u64 a) {
    u64 r; asm("xor.b64 %0, %1, 0x8000000080000000;" : "=l"(r) : "l"(a)); return r;
}

// packed gelu: gelu(y)=0.5y+0.5|y|erf(|y|/sqrt2), A&S 7.1.26 (abs err 1.5e-7)
__device__ __forceinline__ u64 gelu2(u64 y2) {
    u64 ay2 = abs2(y2);
    u64 t2 = mul2(ay2, splat2(0.70710678118654752f));
    u64 d2 = fma2(t2, splat2(0.3275911f), splat2(1.0f));
    float d0, d1; unpack2(d2, d0, d1);
    float v0, v1;
    asm("rcp.approx.f32 %0, %1;" : "=f"(v0) : "f"(d0));
    asm("rcp.approx.f32 %0, %1;" : "=f"(v1) : "f"(d1));
    u64 vv = pack2(v0, v1);
    u64 tt = mul2(t2, t2);
    u64 ag = mul2(tt, splat2(-1.442695040888963f));
    float a0, a1; unpack2(ag, a0, a1);
    float e0, e1;
    asm("ex2.approx.f32 %0, %1;" : "=f"(e0) : "f"(a0));
    asm("ex2.approx.f32 %0, %1;" : "=f"(e1) : "f"(a1));
    u64 ee = pack2(e0, e1);
    u64 r = fma2(vv, splat2(1.061405429f), splat2(-1.453152027f));
    r = fma2(r, vv, splat2(1.421413741f));
    r = fma2(r, vv, splat2(-0.284496736f));
    r = fma2(r, vv, splat2(0.254829592f));
    r = mul2(r, vv);
    u64 E2 = fma2(neg2(r), ee, splat2(1.0f));
    u64 hy = mul2(y2, splat2(0.5f));
    u64 hay = mul2(ay2, splat2(0.5f));
    return fma2(hay, E2, hy);
}

// ---------------- scratch ----------------
__device__ __align__(256) float g_emb[1024 * 768];
__device__ __align__(256) float g_ni[64 * 1539];
__device__ __align__(256) float g_nf[64 * 768];
__device__ __align__(256) float g_agg[64 * 1536];
__device__ __align__(256) float g_upd[64 * 768];
__device__ __align__(256) float g_gram[64 * 16];
__device__ float g_st[64], g_ss[64], g_se[2];
__device__ float g_wts[4 * 256];
__device__ float g_ae0[64], g_ae1[64];
__device__ float g_hasin[64];
__device__ float g_hasedge[4];
__device__ unsigned g_barrier;                        // monotonic; never reset
__device__ __align__(256) float g_AB[1024 * 512];     // A | (Bm + bl1)
__device__ __align__(256) float2 g_mr[4 * 256 * 256]; // (rstd, -mean*rstd)

// global barrier for a 64-block grid (all resident: 64 < 148 SMs).
// monotonic counter: barrier instance = old/64; safe across graph replays.
__device__ __forceinline__ void gbar() {
    __syncthreads();
    __threadfence();
    if (threadIdx.x == 0) {
        unsigned old = atomicAdd(&g_barrier, 1u);
        unsigned target = (old / 64u + 1u) * 64u;
        while (*((volatile unsigned*)&g_barrier) < target) { }
        __threadfence();
    }
    __syncthreads();
}

// ---------------- K1: LayerNorm over H=768 ----------------
__global__ void k_ln0(const float* __restrict__ x, const float* __restrict__ gam,
                      const float* __restrict__ bet) {
    int row = blockIdx.x;
    const float* xr = x + row * 768;
    float* yr = g_emb + row * 768;
    int tid = threadIdx.x;
    float v0 = xr[tid], v1 = xr[tid + 256], v2 = xr[tid + 512];
    float s = v0 + v1 + v2;
    float q = v0 * v0 + v1 * v1 + v2 * v2;
    __shared__ float sh0[8], sh1[8], mv[2];
#pragma unroll
    for (int d = 16; d; d >>= 1) {
        s += __shfl_xor_sync(FULLMASK, s, d);
        q += __shfl_xor_sync(FULLMASK, q, d);
    }
    int w = tid >> 5, ln = tid & 31;
    if (!ln) { sh0[w] = s; sh1[w] = q; }
    __syncthreads();
    if (tid == 0) {
        float ss = 0.f, qq = 0.f;
#pragma unroll
        for (int i = 0; i < 8; i++) { ss += sh0[i]; qq += sh1[i]; }
        float m = ss * (1.f / 768.f);
        float var = qq * (1.f / 768.f) - m * m;
        mv[0] = m; mv[1] = rsqrtf(var + 1e-5f);
    }
    __syncthreads();
    float m = mv[0], r = mv[1];
    yr[tid]       = (v0 - m) * r * gam[tid]       + bet[tid];
    yr[tid + 256] = (v1 - m) * r * gam[tid + 256] + bet[tid + 256];
    yr[tid + 512] = (v2 - m) * r * gam[tid + 512] + bet[tid + 512];
}

// ---------------- tiny-GEMM phase body: out[64,768] = in[64,Kd] @ W + bias ---------
__device__ __forceinline__ void gemm_small_phase(
        float* ws, const float* in, float* out, int Kd,
        const float* __restrict__ W, const float* __restrict__ bias, int relu,
        int blk, int tid) {
    for (int pass = 0; pass < 3; pass++) {
        int c0 = pass * 256 + blk * 4;
        for (int idx = tid; idx < Kd * 4; idx += 256) {
            int k = idx >> 2, c = idx & 3;
            ws[k * 5 + c] = W[k * 768 + c0 + c];
        }
        __syncthreads();
        int w = tid >> 5, lane = tid & 31;
        for (int rr = 0; rr < 8; rr++) {
            int row = (w << 3) + rr;
            const float* ip = in + row * Kd;
            float a0 = 0.f, a1 = 0.f, a2 = 0.f, a3 = 0.f;
            for (int k = lane; k < Kd; k += 32) {
                float x = ip[k];
                const float* p = ws + k * 5;
                a0 = fmaf(x, p[0], a0); a1 = fmaf(x, p[1], a1);
                a2 = fmaf(x, p[2], a2); a3 = fmaf(x, p[3], a3);
            }
            float k1 = (lane & 1) ? a2 : a0, s1 = (lane & 1) ? a0 : a2;
            float k2 = (lane & 1) ? a3 : a1, s2 = (lane & 1) ? a1 : a3;
            float v0 = k1 + __shfl_xor_sync(FULLMASK, s1, 1);
            float v1 = k2 + __shfl_xor_sync(FULLMASK, s2, 1);
            float kk = (lane & 2) ? v1 : v0, ss = (lane & 2) ? v0 : v1;
            float u = kk + __shfl_xor_sync(FULLMASK, ss, 2);
            u += __shfl_xor_sync(FULLMASK, u, 4);
            u += __shfl_xor_sync(FULLMASK, u, 8);
            u += __shfl_xor_sync(FULLMASK, u, 16);
            if (lane < 4) {
                int c = ((lane & 1) << 1) | ((lane >> 1) & 1);
                float r2 = u + bias[c0 + c];
                if (relu) r2 = fmaxf(r2, 0.f);
                out[row * 768 + c0 + c] = r2;
            }
        }
        __syncthreads();
    }
}

// ---------------- K2: persistent triplet mega-kernel (grid 64 x 256) ---------------
__global__ void __launch_bounds__(256) k_triplet(
        const int* __restrict__ ast, const int* __restrict__ aed,
        const int* __restrict__ ost, const int* __restrict__ oed,
        const int* __restrict__ sid, const float* __restrict__ edge,
        const float* __restrict__ Wa, const float* __restrict__ ba,
        const float* __restrict__ W_tp, const float* __restrict__ b_tp,
        const float* __restrict__ W_gat, const float* __restrict__ b_gat) {
    __shared__ float ws[1539 * 5];   // 30.8 KB; reused by softmax phase via alias
    int blk = blockIdx.x, tid = threadIdx.x;

    // ---- phase 1: span means + one-hot (block = bt) ----
    {
        int bt = blk, b = bt >> 4;
        int as_ = ast[bt], ae = aed[bt], os_ = ost[bt], oe = oed[bt];
        float ca = 1.f / (float)(ae - as_ + 1);
        float co = 1.f / (float)(oe - os_ + 1);
        float* ni = g_ni + bt * 1539;
        const float* eb = g_emb + b * 256 * 768;
        for (int h = tid; h < 768; h += 256) {
            float sa = 0.f;
            for (int r = as_; r <= ae; r++) sa += eb[r * 768 + h];
            float so = 0.f;
            for (int r = os_; r <= oe; r++) so += eb[r * 768 + h];
            ni[h] = sa * ca;
            ni[768 + h] = so * co;
        }
        if (tid < 3) ni[1536 + tid] = (sid[bt] - 2 == (int)tid) ? 1.f : 0.f;
    }
    gbar();

    // ---- phase 2: nf = ni @ W_tp + b_tp ----
    gemm_small_phase(ws, g_ni, g_nf, 1539, W_tp, b_tp, 0, blk, tid);
    gbar();

    // ---- phase 3: triplet dots (block = (b,i)); lower 128 threads ----
    if (tid < 128) {
        int i = blk & 15, b = blk >> 4;
        int w = tid >> 5, lane = tid & 31;
        const float* ni = g_nf + (b * 16 + i) * 768;
        float4 av[6];
#pragma unroll
        for (int c = 0; c < 6; c++) av[c] = *(const float4*)(ni + (c * 32 + lane) * 4);
        const float* base = g_nf + b * 16 * 768;
        float acc[4] = {0.f, 0.f, 0.f, 0.f};
#pragma unroll
        for (int jj = 0; jj < 4; jj++) {
            const float* nj = base + (w * 4 + jj) * 768;
#pragma unroll
            for (int c = 0; c < 6; c++) {
                float4 bv = *(const float4*)(nj + (c * 32 + lane) * 4);
                acc[jj] = fmaf(av[c].x, bv.x, acc[jj]);
                acc[jj] = fmaf(av[c].y, bv.y, acc[jj]);
                acc[jj] = fmaf(av[c].z, bv.z, acc[jj]);
                acc[jj] = fmaf(av[c].w, bv.w, acc[jj]);
            }
        }
        {
            float k1 = (lane & 1) ? acc[2] : acc[0], s1 = (lane & 1) ? acc[0] : acc[2];
            float k2 = (lane & 1) ? acc[3] : acc[1], s2 = (lane & 1) ? acc[1] : acc[3];
            float v0 = k1 + __shfl_xor_sync(FULLMASK, s1, 1);
            float v1 = k2 + __shfl_xor_sync(FULLMASK, s2, 1);
            float kk = (lane & 2) ? v1 : v0, ss = (lane & 2) ? v0 : v1;
            float u = kk + __shfl_xor_sync(FULLMASK, ss, 2);
            u += __shfl_xor_sync(FULLMASK, u, 4);
            u += __shfl_xor_sync(FULLMASK, u, 8);
            u += __shfl_xor_sync(FULLMASK, u, 16);
            if (lane < 4) {
                int jj = ((lane & 1) << 1) | ((lane >> 1) & 1);
                g_gram[(b * 16 + i) * 16 + w * 4 + jj] = u;
            }
        }
        if (w == 0) {
            float a1 = 0.f, a2 = 0.f;
#pragma unroll
            for (int c = 0; c < 6; c++) {
                int kb = (c * 32 + lane) * 4;
                float4 w1 = *(const float4*)(Wa + kb);
                float4 w2 = *(const float4*)(Wa + 768 + kb);
                float lx;
                lx = av[c].x > 0.f ? av[c].x : 0.2f * av[c].x; a1 = fmaf(lx, w1.x, a1); a2 = fmaf(lx, w2.x, a2);
                lx = av[c].y > 0.f ? av[c].y : 0.2f * av[c].y; a1 = fmaf(lx, w1.y, a1); a2 = fmaf(lx, w2.y, a2);
                lx = av[c].z > 0.f ? av[c].z : 0.2f * av[c].z; a1 = fmaf(lx, w1.z, a1); a2 = fmaf(lx, w2.z, a2);
                lx = av[c].w > 0.f ? av[c].w : 0.2f * av[c].w; a1 = fmaf(lx, w1.w, a1); a2 = fmaf(lx, w2.w, a2);
            }
            float keep = (lane & 1) ? a2 : a1, send = (lane & 1) ? a1 : a2;
            float v = keep + __shfl_xor_sync(FULLMASK, send, 1);
            v += __shfl_xor_sync(FULLMASK, v, 2);
            v += __shfl_xor_sync(FULLMASK, v, 4);
            v += __shfl_xor_sync(FULLMASK, v, 8);
            v += __shfl_xor_sync(FULLMASK, v, 16);
            if (lane == 0) g_st[b * 16 + i] = v;
            if (lane == 1) g_ss[b * 16 + i] = v;
        }
        if (b == 0 && i < 2 && w == 1) {
            const float* ep = edge + i * 768;
            float a = 0.f;
#pragma unroll
            for (int c = 0; c < 6; c++) {
                int kb = (c * 32 + lane) * 4;
                float4 ev = *(const float4*)(ep + kb);
                float4 w3 = *(const float4*)(Wa + 1536 + kb);
                float lx;
                lx = ev.x > 0.f ? ev.x : 0.2f * ev.x; a = fmaf(lx, w3.x, a);
                lx = ev.y > 0.f ? ev.y : 0.2f * ev.y; a = fmaf(lx, w3.y, a);
                lx = ev.z > 0.f ? ev.z : 0.2f * ev.z; a = fmaf(lx, w3.z, a);
                lx = ev.w > 0.f ? ev.w : 0.2f * ev.w; a = fmaf(lx, w3.w, a);
            }
#pragma unroll
            for (int d = 16; d; d >>= 1) a += __shfl_xor_sync(FULLMASK, a, d);
            if (lane == 0) g_se[i] = a;
        }
    }
    gbar();

    // ---- phase 4: softmax + aggregate (blocks 0..3 only; b = blk) ----
    if (blk < 4) {
        int b = blk;
        float* st_s = ws;            // alias into ws: tiny scratch
        float* ss_s = ws + 16;
        float* se_s = ws + 32;
        float* wts  = ws + 64;       // 256
        float* ae0  = ws + 320;      // 16
        float* ae1  = ws + 336;      // 16
        float* gram_s = ws + 384;    // 256
        int* as_ = (int*)(ws + 640);
        int* ae_ = (int*)(ws + 656);
        int* os_ = (int*)(ws + 672);
        int* oe_ = (int*)(ws + 688);
        if (tid < 16) {
            int bt = b * 16 + tid;
            as_[tid] = ast[bt]; ae_[tid] = aed[bt]; os_[tid] = ost[bt]; oe_[tid] = oed[bt];
            st_s[tid] = g_st[bt]; ss_s[tid] = g_ss[bt];
        }
        if (tid >= 16 && tid < 18) se_s[tid - 16] = g_se[tid - 16];
        if (tid < 256 && tid >= 32) { }  // covered below
        for (int g = tid; g < 256; g += 256) gram_s[g] = g_gram[b * 256 + g];
        __syncthreads();
        bool anyin = false;
        if (tid < 16) {
            int i = tid;
            float bA = ba[0];
            float sc[32];
            float mx = -1e30f;
#pragma unroll
            for (int j = 0; j < 16; j++) {
                bool okji = (j != i) && (gram_s[j * 16 + i] > 0.f);
                bool aeq = (as_[i] == as_[j]) && (ae_[i] == ae_[j]);
                bool oeq = (os_[i] == os_[j]) && (oe_[i] == oe_[j]);
                bool m0 = okji && aeq, m1 = okji && oeq;
                float base2 = st_s[i] + ss_s[j] + bA;
                float s0 = m0 ? base2 + se_s[0] : -1e9f;
                float s1 = m1 ? base2 + se_s[1] : -1e9f;
                sc[2 * j] = s0; sc[2 * j + 1] = s1;
                anyin = anyin || m0 || m1;
                mx = fmaxf(mx, fmaxf(s0, s1));
            }
            float sum = 0.f;
#pragma unroll
            for (int t = 0; t < 32; t++) { float e = expf(sc[t] - mx); sc[t] = e; sum += e; }
            float inv = 1.f / sum;
            float a0s = 0.f, a1s = 0.f;
#pragma unroll
            for (int j = 0; j < 16; j++) {
                float w0 = sc[2 * j] * inv, w1 = sc[2 * j + 1] * inv;
                wts[i * 16 + j] = w0 + w1;
                a0s += w0; a1s += w1;
            }
            ae0[i] = a0s; ae1[i] = a1s;
            g_hasin[b * 16 + i] = anyin ? 1.f : 0.f;
        }
        if (tid < 32) {
            unsigned m = __ballot_sync(FULLMASK, anyin);
            if (tid == 0) g_hasedge[b] = (m & 0xFFFFu) ? 1.f : 0.f;
        }
        __syncthreads();
#pragma unroll
        for (int hs = 0; hs < 3; hs++) {
            int h = hs * 256 + tid;
            float nfh[16];
#pragma unroll
            for (int s = 0; s < 16; s++) nfh[s] = g_nf[(b * 16 + s) * 768 + h];
#pragma unroll
            for (int t = 0; t < 16; t++) {
                float a = 0.f;
#pragma unroll
                for (int s = 0; s < 16; s++) a = fmaf(wts[t * 16 + s], nfh[s], a);
                g_agg[(b * 16 + t) * 1536 + h] = a;
            }
            float e0 = edge[h], e1 = edge[768 + h];
#pragma unroll
            for (int t = 0; t < 16; t++)
                g_agg[(b * 16 + t) * 1536 + 768 + h] = ae0[t] * e0 + ae1[t] * e1;
        }
    }
    gbar();

    // ---- phase 5: upd = relu(agg @ W_gat + b_gat) ----
    gemm_small_phase(ws, g_agg, g_upd, 1536, W_gat, b_gat, 1, blk, tid);
    gbar();

    // ---- phase 6: scatter-add into emb (blocks 0..23; b = blk/6, hz = blk%6) ----
    if (blk < 24 && tid < 128) {
        int b = blk / 6, hz = blk % 6;
        int h = hz * 128 + tid;
        float he = g_hasedge[b];
        for (int t = 0; t < 16; t++) {
            int bt = b * 16 + t;
            int c = (ast[bt] + ost[bt]) >> 1;
            float hi = g_hasin[bt];
            const float* src = (hi > 0.f) ? (g_upd + bt * 768) : (g_nf + bt * 768);
            g_emb[(b * 256 + c) * 768 + h] += src[h] * he;
        }
    }
}

// ---------------- K3: GEMM emb[1024,768] @ Wcat[768,512] (+bl1 on B half) ----------
__global__ void k_gemm(const float* __restrict__ W1, const float* __restrict__ bl1) {
    __shared__ float As[64][16];
    __shared__ float Bs[16][64];
    int bx = blockIdx.x, by = blockIdx.y;
    int tid = threadIdx.x;
    int tx = tid & 15, ty = tid >> 4;
    int row0 = by * 64, col0 = bx * 64;
    int side = col0 >> 8;
    int wcol0 = col0 & 255;
    const float* Wbase = W1 + side * 768 * 256;
    u64 acc2[4][2];
#pragma unroll
    for (int i = 0; i < 4; i++) { acc2[i][0] = 0ull; acc2[i][1] = 0ull; }
    int ar = tid >> 2, ak = (tid & 3) * 4;
    int bk = tid >> 4, bn = (tid & 15) * 4;
    float4 av = *(const float4*)(g_emb + (row0 + ar) * 768 + ak);
    float4 bv = *(const float4*)(Wbase + bk * 256 + wcol0 + bn);
    for (int k0 = 0; k0 < 768; k0 += 16) {
        __syncthreads();
        *(float4*)&As[ar][ak] = av;
        *(float4*)&Bs[bk][bn] = bv;
        __syncthreads();
        if (k0 + 16 < 768) {
            av = *(const float4*)(g_emb + (row0 + ar) * 768 + k0 + 16 + ak);
            bv = *(const float4*)(Wbase + (k0 + 16 + bk) * 256 + wcol0 + bn);
        }
#pragma unroll
        for (int kk = 0; kk < 16; kk++) {
            float4 bv4 = *(const float4*)&Bs[kk][tx * 4];
            u64 b0 = ((u64*)&bv4)[0], b1 = ((u64*)&bv4)[1];
#pragma unroll
            for (int ii = 0; ii < 4; ii++) {
                u64 as = splat2(As[ty * 4 + ii][kk]);
                acc2[ii][0] = fma2(as, b0, acc2[ii][0]);
                acc2[ii][1] = fma2(as, b1, acc2[ii][1]);
            }
        }
    }
    float badd0 = 0.f, badd1 = 0.f, badd2 = 0.f, badd3 = 0.f;
    if (side) {
        const float* bp = bl1 + wcol0 + tx * 4;
        badd0 = bp[0]; badd1 = bp[1]; badd2 = bp[2]; badd3 = bp[3];
    }
#pragma unroll
    for (int ii = 0; ii < 4; ii++) {
        float o0, o1, o2, o3;
        unpack2(acc2[ii][0], o0, o1);
        unpack2(acc2[ii][1], o2, o3);
        float4 o = make_float4(o0 + badd0, o1 + badd1, o2 + badd2, o3 + badd3);
        *(float4*)(g_AB + (size_t)(row0 + ty * 4 + ii) * 512 + col0 + tx * 4) = o;
    }
}

// ---------------- K4: cross dots + inline row stats -> (rstd, -mean*rstd) --------
__global__ void k_dots() {
    __shared__ float As[64][16];
    __shared__ float Cs[64][17];
    __shared__ float sAs[64], qAs[64], sCs[64], qCs[64];
    int bxj = blockIdx.x, byi = blockIdx.y, b = blockIdx.z;
    int tid = threadIdx.x;
    int tx = tid & 15, ty = tid >> 4;
    int lane = tid & 31;
    const float* base = g_AB + (size_t)b * 131072;
    u64 acc2[4][2];
#pragma unroll
    for (int i = 0; i < 4; i++) { acc2[i][0] = 0ull; acc2[i][1] = 0ull; }
    int ar = tid >> 2, ak = (tid & 3) * 4;
    float sA = 0.f, qA = 0.f, sC = 0.f, qC = 0.f;
    float4 av = *(const float4*)(base + (byi * 64 + ar) * 512 + ak);
    float4 cv = *(const float4*)(base + (bxj * 64 + ar) * 512 + 256 + ak);
    for (int k0 = 0; k0 < 256; k0 += 16) {
        sA += (av.x + av.y) + (av.z + av.w);
        qA = fmaf(av.x, av.x, qA); qA = fmaf(av.y, av.y, qA);
        qA = fmaf(av.z, av.z, qA); qA = fmaf(av.w, av.w, qA);
        sC += (cv.x + cv.y) + (cv.z + cv.w);
        qC = fmaf(cv.x, cv.x, qC); qC = fmaf(cv.y, cv.y, qC);
        qC = fmaf(cv.z, cv.z, qC); qC = fmaf(cv.w, cv.w, qC);
        __syncthreads();
        *(float4*)&As[ar][ak] = av;
        Cs[ar][ak] = cv.x; Cs[ar][ak + 1] = cv.y; Cs[ar][ak + 2] = cv.z; Cs[ar][ak + 3] = cv.w;
        __syncthreads();
        if (k0 + 16 < 256) {
            av = *(const float4*)(base + (byi * 64 + ar) * 512 + k0 + 16 + ak);
            cv = *(const float4*)(base + (bxj * 64 + ar) * 512 + 256 + k0 + 16 + ak);
        }
#pragma unroll
        for (int kk = 0; kk < 16; kk++) {
            u64 c0 = pack2(Cs[tx * 4 + 0][kk], Cs[tx * 4 + 1][kk]);
            u64 c1 = pack2(Cs[tx * 4 + 2][kk], Cs[tx * 4 + 3][kk]);
#pragma unroll
            for (int ii = 0; ii < 4; ii++) {
                u64 as = splat2(As[ty * 4 + ii][kk]);
                acc2[ii][0] = fma2(as, c0, acc2[ii][0]);
                acc2[ii][1] = fma2(as, c1, acc2[ii][1]);
            }
        }
    }
    sA += __shfl_xor_sync(FULLMASK, sA, 1); sA += __shfl_xor_sync(FULLMASK, sA, 2);
    qA += __shfl_xor_sync(FULLMASK, qA, 1); qA += __shfl_xor_sync(FULLMASK, qA, 2);
    sC += __shfl_xor_sync(FULLMASK, sC, 1); sC += __shfl_xor_sync(FULLMASK, sC, 2);
    qC += __shfl_xor_sync(FULLMASK, qC, 1); qC += __shfl_xor_sync(FULLMASK, qC, 2);
    __syncthreads();
    if ((lane & 3) == 0) { sAs[ar] = sA; qAs[ar] = qA; sCs[ar] = sC; qCs[ar] = qC; }
    __syncthreads();
    int ib = byi * 64 + ty * 4, jb = bxj * 64 + tx * 4;
#pragma unroll
    for (int ii = 0; ii < 4; ii++) {
        float D0, D1, D2, D3;
        unpack2(acc2[ii][0], D0, D1);
        unpack2(acc2[ii][1], D2, D3);
        float D[4] = {D0, D1, D2, D3};
        float sa = sAs[ty * 4 + ii], qa = qAs[ty * 4 + ii];
#pragma unroll
        for (int jj = 0; jj < 4; jj++) {
            float mean = (sa + sCs[tx * 4 + jj]) * (1.f / 256.f);
            float q = qa + qCs[tx * 4 + jj] + 2.f * D[jj];
            float var = q * (1.f / 256.f) - mean * mean;
            float rstd = rsqrtf(var + 1e-5f);
            g_mr[(size_t)(b * 256 + ib + ii) * 256 + jb + jj] = make_float2(rstd, -mean * rstd);
        }
    }
}

// ---------------- K5: fused add + LN(stats) + packed GELU + [256,8] proj ----------
// grid (256 i, 8 = b*2 + jhalf); 4 warps x 32 j each (R9 form, depth-1 prefetch)
__global__ void k_fused(
        const float* __restrict__ g1, const float* __restrict__ be1,
        const float* __restrict__ Wc, const float* __restrict__ bc,
        const float* __restrict__ Wc1, const float* __restrict__ bc1,
        const float* __restrict__ masks, float* __restrict__ out) {
    int b = blockIdx.y >> 1;
    int jhalf = blockIdx.y & 1;
    int i = blockIdx.x;
    int w = threadIdx.x >> 5, lane = threadIdx.x & 31;
    int j0 = jhalf * 128 + w * 32;

    const float* Arow = g_AB + (size_t)(b * 256 + i) * 512;
    float4 A1 = ((const float4*)Arow)[lane];
    float4 A2 = ((const float4*)Arow)[32 + lane];
    u64 a0p[4] = {((u64*)&A1)[0], ((u64*)&A1)[1], ((u64*)&A2)[0], ((u64*)&A2)[1]};
    float4 G1 = ((const float4*)g1)[lane], G2 = ((const float4*)g1)[32 + lane];
    float4 B1 = ((const float4*)be1)[lane], B2 = ((const float4*)be1)[32 + lane];
    u64 ggp[4] = {((u64*)&G1)[0], ((u64*)&G1)[1], ((u64*)&G2)[0], ((u64*)&G2)[1]};
    u64 bbp[4] = {((u64*)&B1)[0], ((u64*)&B1)[1], ((u64*)&B2)[0], ((u64*)&B2)[1]};

    u64 wcp[4][8];
#pragma unroll
    for (int p = 0; p < 4; p++) {
        int k0 = (p < 2) ? (lane * 4 + p * 2) : (128 + lane * 4 + (p - 2) * 2);
        int k1 = k0 + 1;
#pragma unroll
        for (int c = 0; c < 6; c++) wcp[p][c] = pack2(Wc[k0 * 6 + c], Wc[k1 * 6 + c]);
        wcp[p][6] = pack2(Wc1[k0 * 2], Wc1[k1 * 2]);
        wcp[p][7] = pack2(Wc1[k0 * 2 + 1], Wc1[k1 * 2 + 1]);
    }
    int ch = ((lane & 1) << 2) | (lane & 2) | ((lane >> 2) & 1);
    float myb = (ch < 6) ? bc[ch] : bc1[ch - 6];

    const float* Bbase = g_AB + (size_t)b * 131072 + 256;
    const float2* mrp = g_mr + (size_t)(b * 256 + i) * 256 + j0;
    const float* mrow = masks + (b * 256 + i) * 256;
    float* outp = out + (size_t)((b * 256 + i) * 256) * 8;

    const ulonglong2* Bv = (const ulonglong2*)(Bbase + (size_t)j0 * 512);
    ulonglong2 U = Bv[lane], V = Bv[32 + lane];
    float2 mr = mrp[0];

    for (int jj = 0; jj < 32; jj++) {
        int j = j0 + jj;
        u64 xs[4];
        xs[0] = add2(a0p[0], U.x); xs[1] = add2(a0p[1], U.y);
        xs[2] = add2(a0p[2], V.x); xs[3] = add2(a0p[3], V.y);
        u64 r2 = splat2(mr.x);       // rstd
        u64 nm2 = splat2(mr.y);      // -mean*rstd
        if (jj + 1 < 32) {           // prefetch next B row + stats
            const ulonglong2* Bn = (const ulonglong2*)(Bbase + (size_t)(j + 1) * 512);
            U = Bn[lane]; V = Bn[32 + lane];
            mr = mrp[jj + 1];
        }
        u64 ge[4];
#pragma unroll
        for (int p = 0; p < 4; p++) {
            u64 rg = mul2(ggp[p], r2);
            u64 c2 = fma2(nm2, ggp[p], bbp[p]);
            u64 y2 = fma2(xs[p], rg, c2);
            ge[p] = gelu2(y2);
        }
        u64 acc2[8];
#pragma unroll
        for (int c = 0; c < 8; c++) {
            u64 a = mul2(ge[0], wcp[0][c]);
            a = fma2(ge[1], wcp[1][c], a);
            a = fma2(ge[2], wcp[2][c], a);
            acc2[c] = fma2(ge[3], wcp[3][c], a);
        }
        float acc[8];
#pragma unroll
        for (int c = 0; c < 8; c++) { float ua, ub; unpack2(acc2[c], ua, ub); acc[c] = ua + ub; }
#pragma unroll
        for (int c = 0; c < 4; c++) {
            float keep = (lane & 1) ? acc[c + 4] : acc[c];
            float send = (lane & 1) ? acc[c] : acc[c + 4];
            acc[c] = keep + __shfl_xor_sync(FULLMASK, send, 1);
        }
#pragma unroll
        for (int c = 0; c < 2; c++) {
            float keep = (lane & 2) ? acc[c + 2] : acc[c];
            float send = (lane & 2) ? acc[c] : acc[c + 2];
            acc[c] = keep + __shfl_xor_sync(FULLMASK, send, 2);
        }
        {
            float keep = (lane & 4) ? acc[1] : acc[0];
            float send = (lane & 4) ? acc[0] : acc[1];
            acc[0] = keep + __shfl_xor_sync(FULLMASK, send, 4);
        }
        acc[0] += __shfl_xor_sync(FULLMASK, acc[0], 8);
        acc[0] += __shfl_xor_sync(FULLMASK, acc[0], 16);

        float mval = mrow[j];
        if (lane < 8) outp[j * 8 + ch] = (acc[0] + myb) * mval;
    }
}

extern "C" void kernel_launch(void* const* d_in, const int* in_sizes, int n_in,
                              void* d_out, int out_size) {
    const float* embeddings = (const float*)d_in[0];
    const float* masks      = (const float*)d_in[1];
    const int* asp_st = (const int*)d_in[2];
    const int* asp_ed = (const int*)d_in[3];
    const int* opi_st = (const int*)d_in[4];
    const int* opi_ed = (const int*)d_in[5];
    const int* sent_id = (const int*)d_in[6];
    const float* edge_embed = (const float*)d_in[7];
    const float* W_tp = (const float*)d_in[8];
    const float* b_tp = (const float*)d_in[9];
    const float* W_attn = (const float*)d_in[10];
    const float* b_attn = (const float*)d_in[11];
    const float* W_gat = (const float*)d_in[12];
    const float* b_gat = (const float*)d_in[13];
    const float* gamma0 = (const float*)d_in[14];
    const float* beta0 = (const float*)d_in[15];
    const float* W1 = (const float*)d_in[16];
    const float* bl1 = (const float*)d_in[17];
    const float* gamma1 = (const float*)d_in[18];
    const float* beta1 = (const float*)d_in[19];
    const float* Wc = (const float*)d_in[20];
    const float* bc = (const float*)d_in[21];
    const float* Wc1 = (const float*)d_in[22];
    const float* bc1 = (const float*)d_in[23];
    float* out = (float*)d_out;

    k_ln0<<<1024, 256>>>(embeddings, gamma0, beta0);
    k_triplet<<<64, 256>>>(asp_st, asp_ed, opi_st, opi_ed, sent_id, edge_embed,
                           W_attn, b_attn, W_tp, b_tp, W_gat, b_gat);
    k_gemm<<<dim3(8, 16), 256>>>(W1, bl1);
    k_dots<<<dim3(4, 4, 4), 256>>>();
    k_fused<<<dim3(256, 8), 128>>>(gamma1, beta1, Wc, bc, Wc1, bc1, masks, out);
}

// round 14
// speedup vs baseline: 1.1963x; 1.1963x over previous
#include <cuda_runtime.h>
#include <math.h>

#define FULLMASK 0xffffffffu
typedef unsigned long long u64;

// ---------------- packed f32x2 helpers ----------------
__device__ __forceinline__ u64 pack2(float lo, float hi) {
    u64 r; asm("mov.b64 %0, {%1, %2};" : "=l"(r) : "f"(lo), "f"(hi)); return r;
}
__device__ __forceinline__ u64 splat2(float a) {
    u64 r; asm("mov.b64 %0, {%1, %1};" : "=l"(r) : "f"(a)); return r;
}
__device__ __forceinline__ void unpack2(u64 a, float& x, float& y) {
    asm("mov.b64 {%0, %1}, %2;" : "=f"(x), "=f"(y) : "l"(a));
}
__device__ __forceinline__ u64 fma2(u64 a, u64 b, u64 c) {
    u64 r; asm("fma.rn.f32x2 %0, %1, %2, %3;" : "=l"(r) : "l"(a), "l"(b), "l"(c)); return r;
}
__device__ __forceinline__ u64 add2(u64 a, u64 b) {
    u64 r; asm("add.rn.f32x2 %0, %1, %2;" : "=l"(r) : "l"(a), "l"(b)); return r;
}
__device__ __forceinline__ u64 mul2(u64 a, u64 b) {
    u64 r; asm("mul.rn.f32x2 %0, %1, %2;" : "=l"(r) : "l"(a), "l"(b)); return r;
}
__device__ __forceinline__ u64 abs2(u64 a) {
    u64 r; asm("and.b64 %0, %1, 0x7FFFFFFF7FFFFFFF;" : "=l"(r) : "l"(a)); return r;
}
__device__ __forceinline__ u64 neg2(u64 a) {
    u64 r; asm("xor.b64 %0, %1, 0x8000000080000000;" : "=l"(r) : "l"(a)); return r;
}

// packed gelu: gelu(y)=0.5y+0.5|y|erf(|y|/sqrt2), A&S 7.1.25 3-term (abs err 2.5e-5)
__device__ __forceinline__ u64 gelu2(u64 y2) {
    u64 ay2 = abs2(y2);
    u64 t2 = mul2(ay2, splat2(0.70710678118654752f));
    u64 d2 = fma2(t2, splat2(0.47047f), splat2(1.0f));
    float d0, d1; unpack2(d2, d0, d1);
    float v0, v1;
    asm("rcp.approx.f32 %0, %1;" : "=f"(v0) : "f"(d0));
    asm("rcp.approx.f32 %0, %1;" : "=f"(v1) : "f"(d1));
    u64 vv = pack2(v0, v1);
    u64 tt = mul2(t2, t2);
    u64 ag = mul2(tt, splat2(-1.442695040888963f));
    float a0, a1; unpack2(ag, a0, a1);
    float e0, e1;
    asm("ex2.approx.f32 %0, %1;" : "=f"(e0) : "f"(a0));
    asm("ex2.approx.f32 %0, %1;" : "=f"(e1) : "f"(a1));
    u64 ee = pack2(e0, e1);
    u64 r = fma2(vv, splat2(0.7478556f), splat2(-0.0958798f));
    r = fma2(r, vv, splat2(0.3480242f));
    r = mul2(r, vv);
    u64 E2 = fma2(neg2(r), ee, splat2(1.0f));
    u64 hy = mul2(y2, splat2(0.5f));
    u64 hay = mul2(ay2, splat2(0.5f));
    return fma2(hay, E2, hy);
}

// ---------------- scratch ----------------
__device__ __align__(256) float g_emb[1024 * 768];
__device__ __align__(256) float g_ni[64 * 1539];
__device__ __align__(256) float g_nf[64 * 768];
__device__ __align__(256) float g_agg[64 * 1536];
__device__ __align__(256) float g_upd[64 * 768];
__device__ __align__(256) float g_gram[64 * 16];
__device__ float g_st[64], g_ss[64], g_se[2];
__device__ float g_wts[4 * 256];
__device__ float g_ae0[64], g_ae1[64];
__device__ float g_hasin[64];
__device__ float g_hasedge[4];
__device__ __align__(256) float g_AB[1024 * 512];     // A | (Bm + bl1)
__device__ __align__(256) float2 g_mr[4 * 256 * 256]; // (rstd, -mean*rstd)

// ---------------- K1: LayerNorm over H=768 ----------------
__global__ void k_ln0(const float* __restrict__ x, const float* __restrict__ gam,
                      const float* __restrict__ bet) {
    int row = blockIdx.x;
    const float* xr = x + row * 768;
    float* yr = g_emb + row * 768;
    int tid = threadIdx.x;
    float v0 = xr[tid], v1 = xr[tid + 256], v2 = xr[tid + 512];
    float s = v0 + v1 + v2;
    float q = v0 * v0 + v1 * v1 + v2 * v2;
    __shared__ float sh0[8], sh1[8], mv[2];
#pragma unroll
    for (int d = 16; d; d >>= 1) {
        s += __shfl_xor_sync(FULLMASK, s, d);
        q += __shfl_xor_sync(FULLMASK, q, d);
    }
    int w = tid >> 5, ln = tid & 31;
    if (!ln) { sh0[w] = s; sh1[w] = q; }
    __syncthreads();
    if (tid == 0) {
        float ss = 0.f, qq = 0.f;
#pragma unroll
        for (int i = 0; i < 8; i++) { ss += sh0[i]; qq += sh1[i]; }
        float m = ss * (1.f / 768.f);
        float var = qq * (1.f / 768.f) - m * m;
        mv[0] = m; mv[1] = rsqrtf(var + 1e-5f);
    }
    __syncthreads();
    float m = mv[0], r = mv[1];
    yr[tid]       = (v0 - m) * r * gam[tid]       + bet[tid];
    yr[tid + 256] = (v1 - m) * r * gam[tid + 256] + bet[tid + 256];
    yr[tid + 512] = (v2 - m) * r * gam[tid + 512] + bet[tid + 512];
}

// ---------------- K2: span means + one-hot ----------------
__global__ void k_spans(const int* __restrict__ ast, const int* __restrict__ aed,
                        const int* __restrict__ ost, const int* __restrict__ oed,
                        const int* __restrict__ sid) {
    int bt = blockIdx.x;
    int b = bt >> 4;
    int as_ = ast[bt], ae = aed[bt], os_ = ost[bt], oe = oed[bt];
    float ca = 1.f / (float)(ae - as_ + 1);
    float co = 1.f / (float)(oe - os_ + 1);
    float* ni = g_ni + bt * 1539;
    const float* eb = g_emb + b * 256 * 768;
    for (int h = threadIdx.x; h < 768; h += 256) {
        float sa = 0.f;
        for (int r = as_; r <= ae; r++) sa += eb[r * 768 + h];
        float so = 0.f;
        for (int r = os_; r <= oe; r++) so += eb[r * 768 + h];
        ni[h] = sa * ca;
        ni[768 + h] = so * co;
    }
    if (threadIdx.x < 3)
        ni[1536 + threadIdx.x] = (sid[bt] - 2 == (int)threadIdx.x) ? 1.f : 0.f;
}

// ---------------- K3/K7: tiny GEMM [64,Kd] x W[Kd,768] ----------------
__global__ void k_gemm_small(int which, int Kd, const float* __restrict__ W,
                             const float* __restrict__ bias, int relu) {
    __shared__ float ws[1539 * 5];
    const float* in = (which == 0) ? g_ni : g_agg;
    float* out = (which == 0) ? g_nf : g_upd;
    int c0 = blockIdx.x * 4;
    int tid = threadIdx.x;
    for (int idx = tid; idx < Kd * 4; idx += 256) {
        int k = idx >> 2, c = idx & 3;
        ws[k * 5 + c] = W[k * 768 + c0 + c];
    }
    __syncthreads();
    int w = tid >> 5, lane = tid & 31;
    for (int rr = 0; rr < 8; rr++) {
        int row = (w << 3) + rr;
        const float* ip = in + row * Kd;
        float a0 = 0.f, a1 = 0.f, a2 = 0.f, a3 = 0.f;
        for (int k = lane; k < Kd; k += 32) {
            float x = ip[k];
            const float* p = ws + k * 5;
            a0 = fmaf(x, p[0], a0); a1 = fmaf(x, p[1], a1);
            a2 = fmaf(x, p[2], a2); a3 = fmaf(x, p[3], a3);
        }
        float k1 = (lane & 1) ? a2 : a0, s1 = (lane & 1) ? a0 : a2;
        float k2 = (lane & 1) ? a3 : a1, s2 = (lane & 1) ? a1 : a3;
        float v0 = k1 + __shfl_xor_sync(FULLMASK, s1, 1);
        float v1 = k2 + __shfl_xor_sync(FULLMASK, s2, 1);
        float kk = (lane & 2) ? v1 : v0, ss = (lane & 2) ? v0 : v1;
        float u = kk + __shfl_xor_sync(FULLMASK, ss, 2);
        u += __shfl_xor_sync(FULLMASK, u, 4);
        u += __shfl_xor_sync(FULLMASK, u, 8);
        u += __shfl_xor_sync(FULLMASK, u, 16);
        if (lane < 4) {
            int c = ((lane & 1) << 1) | ((lane >> 1) & 1);
            float r2 = u + bias[c0 + c];
            if (relu) r2 = fmaxf(r2, 0.f);
            out[row * 768 + c0 + c] = r2;
        }
    }
}

// ---------------- K4: parallel triplet dots (float4 loads) ----------------
__global__ void k_tdots(const float* __restrict__ edge, const float* __restrict__ Wa) {
    int i = blockIdx.x, b = blockIdx.y;
    int w = threadIdx.x >> 5, lane = threadIdx.x & 31;
    const float* ni = g_nf + (b * 16 + i) * 768;
    float4 av[6];
#pragma unroll
    for (int c = 0; c < 6; c++) av[c] = *(const float4*)(ni + (c * 32 + lane) * 4);

    const float* base = g_nf + b * 16 * 768;
    float acc[4] = {0.f, 0.f, 0.f, 0.f};
#pragma unroll
    for (int jj = 0; jj < 4; jj++) {
        const float* nj = base + (w * 4 + jj) * 768;
#pragma unroll
        for (int c = 0; c < 6; c++) {
            float4 bv = *(const float4*)(nj + (c * 32 + lane) * 4);
            acc[jj] = fmaf(av[c].x, bv.x, acc[jj]);
            acc[jj] = fmaf(av[c].y, bv.y, acc[jj]);
            acc[jj] = fmaf(av[c].z, bv.z, acc[jj]);
            acc[jj] = fmaf(av[c].w, bv.w, acc[jj]);
        }
    }
    {
        float k1 = (lane & 1) ? acc[2] : acc[0], s1 = (lane & 1) ? acc[0] : acc[2];
        float k2 = (lane & 1) ? acc[3] : acc[1], s2 = (lane & 1) ? acc[1] : acc[3];
        float v0 = k1 + __shfl_xor_sync(FULLMASK, s1, 1);
        float v1 = k2 + __shfl_xor_sync(FULLMASK, s2, 1);
        float kk = (lane & 2) ? v1 : v0, ss = (lane & 2) ? v0 : v1;
        float u = kk + __shfl_xor_sync(FULLMASK, ss, 2);
        u += __shfl_xor_sync(FULLMASK, u, 4);
        u += __shfl_xor_sync(FULLMASK, u, 8);
        u += __shfl_xor_sync(FULLMASK, u, 16);
        if (lane < 4) {
            int jj = ((lane & 1) << 1) | ((lane >> 1) & 1);
            g_gram[(b * 16 + i) * 16 + w * 4 + jj] = u;
        }
    }
    if (w == 0) {
        float a1 = 0.f, a2 = 0.f;
#pragma unroll
        for (int c = 0; c < 6; c++) {
            int kb = (c * 32 + lane) * 4;
            float4 w1 = *(const float4*)(Wa + kb);
            float4 w2 = *(const float4*)(Wa + 768 + kb);
            float lx;
            lx = av[c].x > 0.f ? av[c].x : 0.2f * av[c].x; a1 = fmaf(lx, w1.x, a1); a2 = fmaf(lx, w2.x, a2);
            lx = av[c].y > 0.f ? av[c].y : 0.2f * av[c].y; a1 = fmaf(lx, w1.y, a1); a2 = fmaf(lx, w2.y, a2);
            lx = av[c].z > 0.f ? av[c].z : 0.2f * av[c].z; a1 = fmaf(lx, w1.z, a1); a2 = fmaf(lx, w2.z, a2);
            lx = av[c].w > 0.f ? av[c].w : 0.2f * av[c].w; a1 = fmaf(lx, w1.w, a1); a2 = fmaf(lx, w2.w, a2);
        }
        float keep = (lane & 1) ? a2 : a1, send = (lane & 1) ? a1 : a2;
        float v = keep + __shfl_xor_sync(FULLMASK, send, 1);
        v += __shfl_xor_sync(FULLMASK, v, 2);
        v += __shfl_xor_sync(FULLMASK, v, 4);
        v += __shfl_xor_sync(FULLMASK, v, 8);
        v += __shfl_xor_sync(FULLMASK, v, 16);
        if (lane == 0) g_st[b * 16 + i] = v;
        if (lane == 1) g_ss[b * 16 + i] = v;
    }
    if (b == 0 && i < 2 && w == 1) {
        const float* ep = edge + i * 768;
        float a = 0.f;
#pragma unroll
        for (int c = 0; c < 6; c++) {
            int kb = (c * 32 + lane) * 4;
            float4 ev = *(const float4*)(ep + kb);
            float4 w3 = *(const float4*)(Wa + 1536 + kb);
            float lx;
            lx = ev.x > 0.f ? ev.x : 0.2f * ev.x; a = fmaf(lx, w3.x, a);
            lx = ev.y > 0.f ? ev.y : 0.2f * ev.y; a = fmaf(lx, w3.y, a);
            lx = ev.z > 0.f ? ev.z : 0.2f * ev.z; a = fmaf(lx, w3.z, a);
            lx = ev.w > 0.f ? ev.w : 0.2f * ev.w; a = fmaf(lx, w3.w, a);
        }
#pragma unroll
        for (int d = 16; d; d >>= 1) a += __shfl_xor_sync(FULLMASK, a, d);
        if (lane == 0) g_se[i] = a;
    }
}

// ---------------- K5: softmax over edges ----------------
__global__ void k_soft(const int* __restrict__ ast, const int* __restrict__ aed,
                       const int* __restrict__ ost, const int* __restrict__ oed,
                       const float* __restrict__ ba) {
    int b = blockIdx.x, tid = threadIdx.x;  // 32 threads
    __shared__ float st_s[16], ss_s[16], se_s[2];
    __shared__ int as_[16], ae_[16], os_[16], oe_[16];
    __shared__ float gram_s[256];
    if (tid < 16) {
        int bt = b * 16 + tid;
        as_[tid] = ast[bt]; ae_[tid] = aed[bt]; os_[tid] = ost[bt]; oe_[tid] = oed[bt];
        st_s[tid] = g_st[bt]; ss_s[tid] = g_ss[bt];
    }
    if (tid < 2) se_s[tid] = g_se[tid];
    for (int i = tid; i < 256; i += 32) gram_s[i] = g_gram[b * 256 + i];
    __syncwarp();
    bool anyin = false;
    if (tid < 16) {
        int i = tid;
        float bA = ba[0];
        float sc[32];
        float mx = -1e30f;
#pragma unroll
        for (int j = 0; j < 16; j++) {
            bool okji = (j != i) && (gram_s[j * 16 + i] > 0.f);
            bool aeq = (as_[i] == as_[j]) && (ae_[i] == ae_[j]);
            bool oeq = (os_[i] == os_[j]) && (oe_[i] == oe_[j]);
            bool m0 = okji && aeq, m1 = okji && oeq;
            float base2 = st_s[i] + ss_s[j] + bA;
            float s0 = m0 ? base2 + se_s[0] : -1e9f;
            float s1 = m1 ? base2 + se_s[1] : -1e9f;
            sc[2 * j] = s0; sc[2 * j + 1] = s1;
            anyin = anyin || m0 || m1;
            mx = fmaxf(mx, fmaxf(s0, s1));
        }
        float sum = 0.f;
#pragma unroll
        for (int t = 0; t < 32; t++) { float e = expf(sc[t] - mx); sc[t] = e; sum += e; }
        float inv = 1.f / sum;
        float a0s = 0.f, a1s = 0.f;
#pragma unroll
        for (int j = 0; j < 16; j++) {
            float w0 = sc[2 * j] * inv, w1 = sc[2 * j + 1] * inv;
            g_wts[b * 256 + i * 16 + j] = w0 + w1;
            a0s += w0; a1s += w1;
        }
        g_ae0[b * 16 + i] = a0s;
        g_ae1[b * 16 + i] = a1s;
        g_hasin[b * 16 + i] = anyin ? 1.f : 0.f;
    }
    unsigned m = __ballot_sync(FULLMASK, anyin);
    if (tid == 0) g_hasedge[b] = (m & 0xFFFFu) ? 1.f : 0.f;
}

// ---------------- K6: aggregate ----------------
__global__ void k_agg(const float* __restrict__ edge) {
    int b = blockIdx.x, hz = blockIdx.y, tid = threadIdx.x;  // 128 thr
    __shared__ float wts[256], ae0[16], ae1[16];
    if (tid < 16) { ae0[tid] = g_ae0[b * 16 + tid]; ae1[tid] = g_ae1[b * 16 + tid]; }
    for (int i = tid; i < 256; i += 128) wts[i] = g_wts[b * 256 + i];
    __syncthreads();
    int h = hz * 128 + tid;
    float nfh[16];
#pragma unroll
    for (int s = 0; s < 16; s++) nfh[s] = g_nf[(b * 16 + s) * 768 + h];
#pragma unroll
    for (int t = 0; t < 16; t++) {
        float a = 0.f;
#pragma unroll
        for (int s = 0; s < 16; s++) a = fmaf(wts[t * 16 + s], nfh[s], a);
        g_agg[(b * 16 + t) * 1536 + h] = a;
    }
    float e0 = edge[h], e1 = edge[768 + h];
#pragma unroll
    for (int t = 0; t < 16; t++)
        g_agg[(b * 16 + t) * 1536 + 768 + h] = ae0[t] * e0 + ae1[t] * e1;
}

// ---------------- K8: scatter-add ----------------
__global__ void k_scatter(const int* __restrict__ ast, const int* __restrict__ ost) {
    int b = blockIdx.x, hz = blockIdx.y, tid = threadIdx.x;  // 128 thr
    int h = hz * 128 + tid;
    float he = g_hasedge[b];
    for (int t = 0; t < 16; t++) {
        int bt = b * 16 + t;
        int c = (ast[bt] + ost[bt]) >> 1;
        float hi = g_hasin[bt];
        const float* src = (hi > 0.f) ? (g_upd + bt * 768) : (g_nf + bt * 768);
        g_emb[(b * 256 + c) * 768 + h] += src[h] * he;
    }
}

// ---------------- K9: GEMM emb[1024,768] @ Wcat[768,512] (+bl1 on B half) ----------
__global__ void k_gemm(const float* __restrict__ W1, const float* __restrict__ bl1) {
    __shared__ float As[64][16];
    __shared__ float Bs[16][64];
    int bx = blockIdx.x, by = blockIdx.y;
    int tid = threadIdx.x;
    int tx = tid & 15, ty = tid >> 4;
    int row0 = by * 64, col0 = bx * 64;
    int side = col0 >> 8;
    int wcol0 = col0 & 255;
    const float* Wbase = W1 + side * 768 * 256;
    u64 acc2[4][2];
#pragma unroll
    for (int i = 0; i < 4; i++) { acc2[i][0] = 0ull; acc2[i][1] = 0ull; }
    int ar = tid >> 2, ak = (tid & 3) * 4;
    int bk = tid >> 4, bn = (tid & 15) * 4;
    float4 av = *(const float4*)(g_emb + (row0 + ar) * 768 + ak);
    float4 bv = *(const float4*)(Wbase + bk * 256 + wcol0 + bn);
    for (int k0 = 0; k0 < 768; k0 += 16) {
        __syncthreads();
        *(float4*)&As[ar][ak] = av;
        *(float4*)&Bs[bk][bn] = bv;
        __syncthreads();
        if (k0 + 16 < 768) {
            av = *(const float4*)(g_emb + (row0 + ar) * 768 + k0 + 16 + ak);
            bv = *(const float4*)(Wbase + (k0 + 16 + bk) * 256 + wcol0 + bn);
        }
#pragma unroll
        for (int kk = 0; kk < 16; kk++) {
            float4 bv4 = *(const float4*)&Bs[kk][tx * 4];
            u64 b0 = ((u64*)&bv4)[0], b1 = ((u64*)&bv4)[1];
#pragma unroll
            for (int ii = 0; ii < 4; ii++) {
                u64 as = splat2(As[ty * 4 + ii][kk]);
                acc2[ii][0] = fma2(as, b0, acc2[ii][0]);
                acc2[ii][1] = fma2(as, b1, acc2[ii][1]);
            }
        }
    }
    float badd0 = 0.f, badd1 = 0.f, badd2 = 0.f, badd3 = 0.f;
    if (side) {
        const float* bp = bl1 + wcol0 + tx * 4;
        badd0 = bp[0]; badd1 = bp[1]; badd2 = bp[2]; badd3 = bp[3];
    }
#pragma unroll
    for (int ii = 0; ii < 4; ii++) {
        float o0, o1, o2, o3;
        unpack2(acc2[ii][0], o0, o1);
        unpack2(acc2[ii][1], o2, o3);
        float4 o = make_float4(o0 + badd0, o1 + badd1, o2 + badd2, o3 + badd3);
        *(float4*)(g_AB + (size_t)(row0 + ty * 4 + ii) * 512 + col0 + tx * 4) = o;
    }
}

// ---------------- K10: cross dots (32x64 tiles, 128 blocks) + row stats ----------
__global__ void k_dots() {
    __shared__ float As[32][16];
    __shared__ float Cs[64][17];
    __shared__ float sAs[32], qAs[32], sCs[64], qCs[64];
    int bxj = blockIdx.x, byi = blockIdx.y, b = blockIdx.z;
    int tid = threadIdx.x;
    int tx = tid & 15, ty = tid >> 4;
    const float* base = g_AB + (size_t)b * 131072;
    u64 acc2[2][2];
    acc2[0][0] = acc2[0][1] = acc2[1][0] = acc2[1][1] = 0ull;
    int rr = tid >> 2, rk = (tid & 3) * 4;   // C rows 0..63; A rows = rr (tid<128)
    bool hasA = tid < 128;
    float sA = 0.f, qA = 0.f, sC = 0.f, qC = 0.f;
    float4 av = make_float4(0.f, 0.f, 0.f, 0.f);
    if (hasA) av = *(const float4*)(base + (byi * 32 + rr) * 512 + rk);
    float4 cv = *(const float4*)(base + (bxj * 64 + rr) * 512 + 256 + rk);
    for (int k0 = 0; k0 < 256; k0 += 16) {
        if (hasA) {
            sA += (av.x + av.y) + (av.z + av.w);
            qA = fmaf(av.x, av.x, qA); qA = fmaf(av.y, av.y, qA);
            qA = fmaf(av.z, av.z, qA); qA = fmaf(av.w, av.w, qA);
        }
        sC += (cv.x + cv.y) + (cv.z + cv.w);
        qC = fmaf(cv.x, cv.x, qC); qC = fmaf(cv.y, cv.y, qC);
        qC = fmaf(cv.z, cv.z, qC); qC = fmaf(cv.w, cv.w, qC);
        __syncthreads();
        if (hasA) *(float4*)&As[rr][rk] = av;
        Cs[rr][rk] = cv.x; Cs[rr][rk + 1] = cv.y; Cs[rr][rk + 2] = cv.z; Cs[rr][rk + 3] = cv.w;
        __syncthreads();
        if (k0 + 16 < 256) {
            if (hasA) av = *(const float4*)(base + (byi * 32 + rr) * 512 + k0 + 16 + rk);
            cv = *(const float4*)(base + (bxj * 64 + rr) * 512 + 256 + k0 + 16 + rk);
        }
#pragma unroll
        for (int kk = 0; kk < 16; kk++) {
            u64 c0 = pack2(Cs[tx * 4 + 0][kk], Cs[tx * 4 + 1][kk]);
            u64 c1 = pack2(Cs[tx * 4 + 2][kk], Cs[tx * 4 + 3][kk]);
#pragma unroll
            for (int ii = 0; ii < 2; ii++) {
                u64 as = splat2(As[ty * 2 + ii][kk]);
                acc2[ii][0] = fma2(as, c0, acc2[ii][0]);
                acc2[ii][1] = fma2(as, c1, acc2[ii][1]);
            }
        }
    }
    sA += __shfl_xor_sync(FULLMASK, sA, 1); sA += __shfl_xor_sync(FULLMASK, sA, 2);
    qA += __shfl_xor_sync(FULLMASK, qA, 1); qA += __shfl_xor_sync(FULLMASK, qA, 2);
    sC += __shfl_xor_sync(FULLMASK, sC, 1); sC += __shfl_xor_sync(FULLMASK, sC, 2);
    qC += __shfl_xor_sync(FULLMASK, qC, 1); qC += __shfl_xor_sync(FULLMASK, qC, 2);
    __syncthreads();
    if ((tid & 3) == 0) {
        if (hasA) { sAs[rr] = sA; qAs[rr] = qA; }
        sCs[rr] = sC; qCs[rr] = qC;
    }
    __syncthreads();
    int ib = byi * 32 + ty * 2, jb = bxj * 64 + tx * 4;
#pragma unroll
    for (int ii = 0; ii < 2; ii++) {
        float D0, D1, D2, D3;
        unpack2(acc2[ii][0], D0, D1);
        unpack2(acc2[ii][1], D2, D3);
        float D[4] = {D0, D1, D2, D3};
        float sa = sAs[ty * 2 + ii], qa = qAs[ty * 2 + ii];
#pragma unroll
        for (int jj = 0; jj < 4; jj++) {
            float mean = (sa + sCs[tx * 4 + jj]) * (1.f / 256.f);
            float q = qa + qCs[tx * 4 + jj] + 2.f * D[jj];
            float var = q * (1.f / 256.f) - mean * mean;
            float rstd = rsqrtf(var + 1e-5f);
            g_mr[(size_t)(b * 256 + ib + ii) * 256 + jb + jj] = make_float2(rstd, -mean * rstd);
        }
    }
}

// ---------------- K11: fused add + LN(stats) + packed GELU + [256,8] proj ----------
// grid (256 i, 8 = b*2 + jhalf); 4 warps x 32 j each (R9 form)
__global__ void k_fused(
        const float* __restrict__ g1, const float* __restrict__ be1,
        const float* __restrict__ Wc, const float* __restrict__ bc,
        const float* __restrict__ Wc1, const float* __restrict__ bc1,
        const float* __restrict__ masks, float* __restrict__ out) {
    int b = blockIdx.y >> 1;
    int jhalf = blockIdx.y & 1;
    int i = blockIdx.x;
    int w = threadIdx.x >> 5, lane = threadIdx.x & 31;
    int j0 = jhalf * 128 + w * 32;

    const float* Arow = g_AB + (size_t)(b * 256 + i) * 512;
    float4 A1 = ((const float4*)Arow)[lane];
    float4 A2 = ((const float4*)Arow)[32 + lane];
    u64 a0p[4] = {((u64*)&A1)[0], ((u64*)&A1)[1], ((u64*)&A2)[0], ((u64*)&A2)[1]};
    float4 G1 = ((const float4*)g1)[lane], G2 = ((const float4*)g1)[32 + lane];
    float4 B1 = ((const float4*)be1)[lane], B2 = ((const float4*)be1)[32 + lane];
    u64 ggp[4] = {((u64*)&G1)[0], ((u64*)&G1)[1], ((u64*)&G2)[0], ((u64*)&G2)[1]};
    u64 bbp[4] = {((u64*)&B1)[0], ((u64*)&B1)[1], ((u64*)&B2)[0], ((u64*)&B2)[1]};

    u64 wcp[4][8];
#pragma unroll
    for (int p = 0; p < 4; p++) {
        int k0 = (p < 2) ? (lane * 4 + p * 2) : (128 + lane * 4 + (p - 2) * 2);
        int k1 = k0 + 1;
#pragma unroll
        for (int c = 0; c < 6; c++) wcp[p][c] = pack2(Wc[k0 * 6 + c], Wc[k1 * 6 + c]);
        wcp[p][6] = pack2(Wc1[k0 * 2], Wc1[k1 * 2]);
        wcp[p][7] = pack2(Wc1[k0 * 2 + 1], Wc1[k1 * 2 + 1]);
    }
    int ch = ((lane & 1) << 2) | (lane & 2) | ((lane >> 2) & 1);
    float myb = (ch < 6) ? bc[ch] : bc1[ch - 6];

    const float* Bbase = g_AB + (size_t)b * 131072 + 256;
    const float2* mrp = g_mr + (size_t)(b * 256 + i) * 256 + j0;
    const float* mrow = masks + (b * 256 + i) * 256;
    float* outp = out + (size_t)((b * 256 + i) * 256) * 8;

    const ulonglong2* Bv = (const ulonglong2*)(Bbase + (size_t)j0 * 512);
    ulonglong2 U = Bv[lane], V = Bv[32 + lane];
    float2 mr = mrp[0];

    for (int jj = 0; jj < 32; jj++) {
        int j = j0 + jj;
        u64 xs[4];
        xs[0] = add2(a0p[0], U.x); xs[1] = add2(a0p[1], U.y);
        xs[2] = add2(a0p[2], V.x); xs[3] = add2(a0p[3], V.y);
        u64 r2 = splat2(mr.x);       // rstd
        u64 nm2 = splat2(mr.y);      // -mean*rstd
        if (jj + 1 < 32) {           // prefetch next B row + stats
            const ulonglong2* Bn = (const ulonglong2*)(Bbase + (size_t)(j + 1) * 512);
            U = Bn[lane]; V = Bn[32 + lane];
            mr = mrp[jj + 1];
        }
        u64 ge[4];
#pragma unroll
        for (int p = 0; p < 4; p++) {
            u64 rg = mul2(ggp[p], r2);
            u64 c2 = fma2(nm2, ggp[p], bbp[p]);
            u64 y2 = fma2(xs[p], rg, c2);
            ge[p] = gelu2(y2);
        }
        u64 acc2[8];
#pragma unroll
        for (int c = 0; c < 8; c++) {
            u64 a = mul2(ge[0], wcp[0][c]);
            a = fma2(ge[1], wcp[1][c], a);
            a = fma2(ge[2], wcp[2][c], a);
            acc2[c] = fma2(ge[3], wcp[3][c], a);
        }
        float acc[8];
#pragma unroll
        for (int c = 0; c < 8; c++) { float ua, ub; unpack2(acc2[c], ua, ub); acc[c] = ua + ub; }
#pragma unroll
        for (int c = 0; c < 4; c++) {
            float keep = (lane & 1) ? acc[c + 4] : acc[c];
            float send = (lane & 1) ? acc[c] : acc[c + 4];
            acc[c] = keep + __shfl_xor_sync(FULLMASK, send, 1);
        }
#pragma unroll
        for (int c = 0; c < 2; c++) {
            float keep = (lane & 2) ? acc[c + 2] : acc[c];
            float send = (lane & 2) ? acc[c] : acc[c + 2];
            acc[c] = keep + __shfl_xor_sync(FULLMASK, send, 2);
        }
        {
            float keep = (lane & 4) ? acc[1] : acc[0];
            float send = (lane & 4) ? acc[0] : acc[1];
            acc[0] = keep + __shfl_xor_sync(FULLMASK, send, 4);
        }
        acc[0] += __shfl_xor_sync(FULLMASK, acc[0], 8);
        acc[0] += __shfl_xor_sync(FULLMASK, acc[0], 16);

        float mval = mrow[j];
        if (lane < 8) outp[j * 8 + ch] = (acc[0] + myb) * mval;
    }
}

extern "C" void kernel_launch(void* const* d_in, const int* in_sizes, int n_in,
                              void* d_out, int out_size) {
    const float* embeddings = (const float*)d_in[0];
    const float* masks      = (const float*)d_in[1];
    const int* asp_st = (const int*)d_in[2];
    const int* asp_ed = (const int*)d_in[3];
    const int* opi_st = (const int*)d_in[4];
    const int* opi_ed = (const int*)d_in[5];
    const int* sent_id = (const int*)d_in[6];
    const float* edge_embed = (const float*)d_in[7];
    const float* W_tp = (const float*)d_in[8];
    const float* b_tp = (const float*)d_in[9];
    const float* W_attn = (const float*)d_in[10];
    const float* b_attn = (const float*)d_in[11];
    const float* W_gat = (const float*)d_in[12];
    const float* b_gat = (const float*)d_in[13];
    const float* gamma0 = (const float*)d_in[14];
    const float* beta0 = (const float*)d_in[15];
    const float* W1 = (const float*)d_in[16];
    const float* bl1 = (const float*)d_in[17];
    const float* gamma1 = (const float*)d_in[18];
    const float* beta1 = (const float*)d_in[19];
    const float* Wc = (const float*)d_in[20];
    const float* bc = (const float*)d_in[21];
    const float* Wc1 = (const float*)d_in[22];
    const float* bc1 = (const float*)d_in[23];
    float* out = (float*)d_out;

    k_ln0<<<1024, 256>>>(embeddings, gamma0, beta0);
    k_spans<<<64, 256>>>(asp_st, asp_ed, opi_st, opi_ed, sent_id);
    k_gemm_small<<<192, 256>>>(0, 1539, W_tp, b_tp, 0);
    k_tdots<<<dim3(16, 4), 128>>>(edge_embed, W_attn);
    k_soft<<<4, 32>>>(asp_st, asp_ed, opi_st, opi_ed, b_attn);
    k_agg<<<dim3(4, 6), 128>>>(edge_embed);
    k_gemm_small<<<192, 256>>>(1, 1536, W_gat, b_gat, 1);
    k_scatter<<<dim3(4, 6), 128>>>(asp_st, opi_st);
    k_gemm<<<dim3(8, 16), 256>>>(W1, bl1);
    k_dots<<<dim3(4, 8, 4), 256>>>();
    k_fused<<<dim3(256, 8), 128>>>(gamma1, beta1, Wc, bc, Wc1, bc1, masks, out);
}

// round 15
// speedup vs baseline: 1.2040x; 1.0065x over previous
#include <cuda_runtime.h>
#include <math.h>

#define FULLMASK 0xffffffffu
typedef unsigned long long u64;

// ---------------- packed f32x2 helpers ----------------
__device__ __forceinline__ u64 pack2(float lo, float hi) {
    u64 r; asm("mov.b64 %0, {%1, %2};" : "=l"(r) : "f"(lo), "f"(hi)); return r;
}
__device__ __forceinline__ u64 splat2(float a) {
    u64 r; asm("mov.b64 %0, {%1, %1};" : "=l"(r) : "f"(a)); return r;
}
__device__ __forceinline__ void unpack2(u64 a, float& x, float& y) {
    asm("mov.b64 {%0, %1}, %2;" : "=f"(x), "=f"(y) : "l"(a));
}
__device__ __forceinline__ u64 fma2(u64 a, u64 b, u64 c) {
    u64 r; asm("fma.rn.f32x2 %0, %1, %2, %3;" : "=l"(r) : "l"(a), "l"(b), "l"(c)); return r;
}
__device__ __forceinline__ u64 add2(u64 a, u64 b) {
    u64 r; asm("add.rn.f32x2 %0, %1, %2;" : "=l"(r) : "l"(a), "l"(b)); return r;
}
__device__ __forceinline__ u64 mul2(u64 a, u64 b) {
    u64 r; asm("mul.rn.f32x2 %0, %1, %2;" : "=l"(r) : "l"(a), "l"(b)); return r;
}
__device__ __forceinline__ u64 abs2(u64 a) {
    u64 r; asm("and.b64 %0, %1, 0x7FFFFFFF7FFFFFFF;" : "=l"(r) : "l"(a)); return r;
}
__device__ __forceinline__ u64 neg2(u64 a) {
    u64 r; asm("xor.b64 %0, %1, 0x8000000080000000;" : "=l"(r) : "l"(a)); return r;
}

// packed DOUBLE gelu: returns 2*gelu(y) = y + |y|*erf(|y|/sqrt2).
// A&S 7.1.25 3-term (abs err 2.5e-5). The 0.5 is folded into the projection
// weights. d = 1 + 0.47047*(|y|/sqrt2) computed directly from |y|;
// exp arg = -(y^2/2)*log2(e) computed directly from y^2.
__device__ __forceinline__ u64 gelu2x(u64 y2) {
    u64 ay2 = abs2(y2);
    u64 d2 = fma2(ay2, splat2(0.33267212f), splat2(1.0f));   // 0.47047/sqrt2
    float d0, d1; unpack2(d2, d0, d1);
    float v0, v1;
    asm("rcp.approx.f32 %0, %1;" : "=f"(v0) : "f"(d0));
    asm("rcp.approx.f32 %0, %1;" : "=f"(v1) : "f"(d1));
    u64 vv = pack2(v0, v1);
    u64 yy = mul2(y2, y2);
    u64 ag = mul2(yy, splat2(-0.72134752044f));              // -log2(e)/2
    float a0, a1; unpack2(ag, a0, a1);
    float e0, e1;
    asm("ex2.approx.f32 %0, %1;" : "=f"(e0) : "f"(a0));
    asm("ex2.approx.f32 %0, %1;" : "=f"(e1) : "f"(a1));
    u64 ee = pack2(e0, e1);
    u64 r = fma2(vv, splat2(0.7478556f), splat2(-0.0958798f));
    r = fma2(r, vv, splat2(0.3480242f));
    r = mul2(r, vv);
    u64 E2 = fma2(neg2(r), ee, splat2(1.0f));                // erf(t)
    return fma2(ay2, E2, y2);                                // y + |y|*erf = 2*gelu
}

// ---------------- scratch ----------------
__device__ __align__(256) float g_emb[1024 * 768];
__device__ __align__(256) float g_ni[64 * 1539];
__device__ __align__(256) float g_nf[64 * 768];
__device__ __align__(256) float g_agg[64 * 1536];
__device__ __align__(256) float g_upd[64 * 768];
__device__ __align__(256) float g_gram[64 * 16];
__device__ float g_st[64], g_ss[64], g_se[2];
__device__ float g_hasin[64];
__device__ float g_hasedge[4];
__device__ __align__(256) float g_AB[1024 * 512];     // A | (Bm + bl1)
__device__ __align__(256) float2 g_mr[4 * 256 * 256]; // (rstd, -mean*rstd)

// ---------------- K1: LayerNorm over H=768 ----------------
__global__ void k_ln0(const float* __restrict__ x, const float* __restrict__ gam,
                      const float* __restrict__ bet) {
    int row = blockIdx.x;
    const float* xr = x + row * 768;
    float* yr = g_emb + row * 768;
    int tid = threadIdx.x;
    float v0 = xr[tid], v1 = xr[tid + 256], v2 = xr[tid + 512];
    float s = v0 + v1 + v2;
    float q = v0 * v0 + v1 * v1 + v2 * v2;
    __shared__ float sh0[8], sh1[8], mv[2];
#pragma unroll
    for (int d = 16; d; d >>= 1) {
        s += __shfl_xor_sync(FULLMASK, s, d);
        q += __shfl_xor_sync(FULLMASK, q, d);
    }
    int w = tid >> 5, ln = tid & 31;
    if (!ln) { sh0[w] = s; sh1[w] = q; }
    __syncthreads();
    if (tid == 0) {
        float ss = 0.f, qq = 0.f;
#pragma unroll
        for (int i = 0; i < 8; i++) { ss += sh0[i]; qq += sh1[i]; }
        float m = ss * (1.f / 768.f);
        float var = qq * (1.f / 768.f) - m * m;
        mv[0] = m; mv[1] = rsqrtf(var + 1e-5f);
    }
    __syncthreads();
    float m = mv[0], r = mv[1];
    yr[tid]       = (v0 - m) * r * gam[tid]       + bet[tid];
    yr[tid + 256] = (v1 - m) * r * gam[tid + 256] + bet[tid + 256];
    yr[tid + 512] = (v2 - m) * r * gam[tid + 512] + bet[tid + 512];
}

// ---------------- K2: span means + one-hot ----------------
__global__ void k_spans(const int* __restrict__ ast, const int* __restrict__ aed,
                        const int* __restrict__ ost, const int* __restrict__ oed,
                        const int* __restrict__ sid) {
    int bt = blockIdx.x;
    int b = bt >> 4;
    int as_ = ast[bt], ae = aed[bt], os_ = ost[bt], oe = oed[bt];
    float ca = 1.f / (float)(ae - as_ + 1);
    float co = 1.f / (float)(oe - os_ + 1);
    float* ni = g_ni + bt * 1539;
    const float* eb = g_emb + b * 256 * 768;
    for (int h = threadIdx.x; h < 768; h += 256) {
        float sa = 0.f;
        for (int r = as_; r <= ae; r++) sa += eb[r * 768 + h];
        float so = 0.f;
        for (int r = os_; r <= oe; r++) so += eb[r * 768 + h];
        ni[h] = sa * ca;
        ni[768 + h] = so * co;
    }
    if (threadIdx.x < 3)
        ni[1536 + threadIdx.x] = (sid[bt] - 2 == (int)threadIdx.x) ? 1.f : 0.f;
}

// ---------------- K3/K6: tiny GEMM [64,Kd] x W[Kd,768] ----------------
__global__ void k_gemm_small(int which, int Kd, const float* __restrict__ W,
                             const float* __restrict__ bias, int relu) {
    __shared__ float ws[1539 * 5];
    const float* in = (which == 0) ? g_ni : g_agg;
    float* out = (which == 0) ? g_nf : g_upd;
    int c0 = blockIdx.x * 4;
    int tid = threadIdx.x;
    for (int idx = tid; idx < Kd * 4; idx += 256) {
        int k = idx >> 2, c = idx & 3;
        ws[k * 5 + c] = W[k * 768 + c0 + c];
    }
    __syncthreads();
    int w = tid >> 5, lane = tid & 31;
    for (int rr = 0; rr < 8; rr++) {
        int row = (w << 3) + rr;
        const float* ip = in + row * Kd;
        float a0 = 0.f, a1 = 0.f, a2 = 0.f, a3 = 0.f;
        for (int k = lane; k < Kd; k += 32) {
            float x = ip[k];
            const float* p = ws + k * 5;
            a0 = fmaf(x, p[0], a0); a1 = fmaf(x, p[1], a1);
            a2 = fmaf(x, p[2], a2); a3 = fmaf(x, p[3], a3);
        }
        float k1 = (lane & 1) ? a2 : a0, s1 = (lane & 1) ? a0 : a2;
        float k2 = (lane & 1) ? a3 : a1, s2 = (lane & 1) ? a1 : a3;
        float v0 = k1 + __shfl_xor_sync(FULLMASK, s1, 1);
        float v1 = k2 + __shfl_xor_sync(FULLMASK, s2, 1);
        float kk = (lane & 2) ? v1 : v0, ss = (lane & 2) ? v0 : v1;
        float u = kk + __shfl_xor_sync(FULLMASK, ss, 2);
        u += __shfl_xor_sync(FULLMASK, u, 4);
        u += __shfl_xor_sync(FULLMASK, u, 8);
        u += __shfl_xor_sync(FULLMASK, u, 16);
        if (lane < 4) {
            int c = ((lane & 1) << 1) | ((lane >> 1) & 1);
            float r2 = u + bias[c0 + c];
            if (relu) r2 = fmaxf(r2, 0.f);
            out[row * 768 + c0 + c] = r2;
        }
    }
}

// ---------------- K4: parallel triplet dots (float4 loads) ----------------
__global__ void k_tdots(const float* __restrict__ edge, const float* __restrict__ Wa) {
    int i = blockIdx.x, b = blockIdx.y;
    int w = threadIdx.x >> 5, lane = threadIdx.x & 31;
    const float* ni = g_nf + (b * 16 + i) * 768;
    float4 av[6];
#pragma unroll
    for (int c = 0; c < 6; c++) av[c] = *(const float4*)(ni + (c * 32 + lane) * 4);

    const float* base = g_nf + b * 16 * 768;
    float acc[4] = {0.f, 0.f, 0.f, 0.f};
#pragma unroll
    for (int jj = 0; jj < 4; jj++) {
        const float* nj = base + (w * 4 + jj) * 768;
#pragma unroll
        for (int c = 0; c < 6; c++) {
            float4 bv = *(const float4*)(nj + (c * 32 + lane) * 4);
            acc[jj] = fmaf(av[c].x, bv.x, acc[jj]);
            acc[jj] = fmaf(av[c].y, bv.y, acc[jj]);
            acc[jj] = fmaf(av[c].z, bv.z, acc[jj]);
            acc[jj] = fmaf(av[c].w, bv.w, acc[jj]);
        }
    }
    {
        float k1 = (lane & 1) ? acc[2] : acc[0], s1 = (lane & 1) ? acc[0] : acc[2];
        float k2 = (lane & 1) ? acc[3] : acc[1], s2 = (lane & 1) ? acc[1] : acc[3];
        float v0 = k1 + __shfl_xor_sync(FULLMASK, s1, 1);
        float v1 = k2 + __shfl_xor_sync(FULLMASK, s2, 1);
        float kk = (lane & 2) ? v1 : v0, ss = (lane & 2) ? v0 : v1;
        float u = kk + __shfl_xor_sync(FULLMASK, ss, 2);
        u += __shfl_xor_sync(FULLMASK, u, 4);
        u += __shfl_xor_sync(FULLMASK, u, 8);
        u += __shfl_xor_sync(FULLMASK, u, 16);
        if (lane < 4) {
            int jj = ((lane & 1) << 1) | ((lane >> 1) & 1);
            g_gram[(b * 16 + i) * 16 + w * 4 + jj] = u;
        }
    }
    if (w == 0) {
        float a1 = 0.f, a2 = 0.f;
#pragma unroll
        for (int c = 0; c < 6; c++) {
            int kb = (c * 32 + lane) * 4;
            float4 w1 = *(const float4*)(Wa + kb);
            float4 w2 = *(const float4*)(Wa + 768 + kb);
            float lx;
            lx = av[c].x > 0.f ? av[c].x : 0.2f * av[c].x; a1 = fmaf(lx, w1.x, a1); a2 = fmaf(lx, w2.x, a2);
            lx = av[c].y > 0.f ? av[c].y : 0.2f * av[c].y; a1 = fmaf(lx, w1.y, a1); a2 = fmaf(lx, w2.y, a2);
            lx = av[c].z > 0.f ? av[c].z : 0.2f * av[c].z; a1 = fmaf(lx, w1.z, a1); a2 = fmaf(lx, w2.z, a2);
            lx = av[c].w > 0.f ? av[c].w : 0.2f * av[c].w; a1 = fmaf(lx, w1.w, a1); a2 = fmaf(lx, w2.w, a2);
        }
        float keep = (lane & 1) ? a2 : a1, send = (lane & 1) ? a1 : a2;
        float v = keep + __shfl_xor_sync(FULLMASK, send, 1);
        v += __shfl_xor_sync(FULLMASK, v, 2);
        v += __shfl_xor_sync(FULLMASK, v, 4);
        v += __shfl_xor_sync(FULLMASK, v, 8);
        v += __shfl_xor_sync(FULLMASK, v, 16);
        if (lane == 0) g_st[b * 16 + i] = v;
        if (lane == 1) g_ss[b * 16 + i] = v;
    }
    if (b == 0 && i < 2 && w == 1) {
        const float* ep = edge + i * 768;
        float a = 0.f;
#pragma unroll
        for (int c = 0; c < 6; c++) {
            int kb = (c * 32 + lane) * 4;
            float4 ev = *(const float4*)(ep + kb);
            float4 w3 = *(const float4*)(Wa + 1536 + kb);
            float lx;
            lx = ev.x > 0.f ? ev.x : 0.2f * ev.x; a = fmaf(lx, w3.x, a);
            lx = ev.y > 0.f ? ev.y : 0.2f * ev.y; a = fmaf(lx, w3.y, a);
            lx = ev.z > 0.f ? ev.z : 0.2f * ev.z; a = fmaf(lx, w3.z, a);
            lx = ev.w > 0.f ? ev.w : 0.2f * ev.w; a = fmaf(lx, w3.w, a);
        }
#pragma unroll
        for (int d = 16; d; d >>= 1) a += __shfl_xor_sync(FULLMASK, a, d);
        if (lane == 0) g_se[i] = a;
    }
}

// ---------------- K5: aggregate with inlined softmax (grid (4,6) x 128) -----------
// each block recomputes the (tiny) softmax for its batch; 6 blocks/b write
// identical g_hasin/g_hasedge values (benign deterministic same-value race).
__global__ void k_agg(const int* __restrict__ ast, const int* __restrict__ aed,
                      const int* __restrict__ ost, const int* __restrict__ oed,
                      const float* __restrict__ edge, const float* __restrict__ ba) {
    int b = blockIdx.x, hz = blockIdx.y, tid = threadIdx.x;  // 128 thr
    __shared__ float wts[256], ae0[16], ae1[16];
    __shared__ float st_s[16], ss_s[16], se_s[2];
    __shared__ int as_[16], ae_[16], os_[16], oe_[16];
    __shared__ float gram_s[256];
    if (tid < 16) {
        int bt = b * 16 + tid;
        as_[tid] = ast[bt]; ae_[tid] = aed[bt]; os_[tid] = ost[bt]; oe_[tid] = oed[bt];
        st_s[tid] = g_st[bt]; ss_s[tid] = g_ss[bt];
    }
    if (tid >= 16 && tid < 18) se_s[tid - 16] = g_se[tid - 16];
    for (int i = tid; i < 256; i += 128) gram_s[i] = g_gram[b * 256 + i];
    __syncthreads();
    bool anyin = false;
    if (tid < 16) {
        int i = tid;
        float bA = ba[0];
        float sc[32];
        float mx = -1e30f;
#pragma unroll
        for (int j = 0; j < 16; j++) {
            bool okji = (j != i) && (gram_s[j * 16 + i] > 0.f);
            bool aeq = (as_[i] == as_[j]) && (ae_[i] == ae_[j]);
            bool oeq = (os_[i] == os_[j]) && (oe_[i] == oe_[j]);
            bool m0 = okji && aeq, m1 = okji && oeq;
            float base2 = st_s[i] + ss_s[j] + bA;
            float s0 = m0 ? base2 + se_s[0] : -1e9f;
            float s1 = m1 ? base2 + se_s[1] : -1e9f;
            sc[2 * j] = s0; sc[2 * j + 1] = s1;
            anyin = anyin || m0 || m1;
            mx = fmaxf(mx, fmaxf(s0, s1));
        }
        float sum = 0.f;
#pragma unroll
        for (int t = 0; t < 32; t++) { float e = expf(sc[t] - mx); sc[t] = e; sum += e; }
        float inv = 1.f / sum;
        float a0s = 0.f, a1s = 0.f;
#pragma unroll
        for (int j = 0; j < 16; j++) {
            float w0 = sc[2 * j] * inv, w1 = sc[2 * j + 1] * inv;
            wts[i * 16 + j] = w0 + w1;
            a0s += w0; a1s += w1;
        }
        ae0[i] = a0s; ae1[i] = a1s;
        g_hasin[b * 16 + i] = anyin ? 1.f : 0.f;
    }
    if (tid < 32) {
        unsigned m = __ballot_sync(FULLMASK, anyin);
        if (tid == 0) g_hasedge[b] = (m & 0xFFFFu) ? 1.f : 0.f;
    }
    __syncthreads();
    int h = hz * 128 + tid;
    float nfh[16];
#pragma unroll
    for (int s = 0; s < 16; s++) nfh[s] = g_nf[(b * 16 + s) * 768 + h];
#pragma unroll
    for (int t = 0; t < 16; t++) {
        float a = 0.f;
#pragma unroll
        for (int s = 0; s < 16; s++) a = fmaf(wts[t * 16 + s], nfh[s], a);
        g_agg[(b * 16 + t) * 1536 + h] = a;
    }
    float e0 = edge[h], e1 = edge[768 + h];
#pragma unroll
    for (int t = 0; t < 16; t++)
        g_agg[(b * 16 + t) * 1536 + 768 + h] = ae0[t] * e0 + ae1[t] * e1;
}

// ---------------- K7: scatter-add ----------------
__global__ void k_scatter(const int* __restrict__ ast, const int* __restrict__ ost) {
    int b = blockIdx.x, hz = blockIdx.y, tid = threadIdx.x;  // 128 thr
    int h = hz * 128 + tid;
    float he = g_hasedge[b];
    for (int t = 0; t < 16; t++) {
        int bt = b * 16 + t;
        int c = (ast[bt] + ost[bt]) >> 1;
        float hi = g_hasin[bt];
        const float* src = (hi > 0.f) ? (g_upd + bt * 768) : (g_nf + bt * 768);
        g_emb[(b * 256 + c) * 768 + h] += src[h] * he;
    }
}

// ---------------- K8: GEMM emb[1024,768] @ Wcat[768,512] (+bl1 on B half) ----------
__global__ void k_gemm(const float* __restrict__ W1, const float* __restrict__ bl1) {
    __shared__ float As[64][16];
    __shared__ float Bs[16][64];
    int bx = blockIdx.x, by = blockIdx.y;
    int tid = threadIdx.x;
    int tx = tid & 15, ty = tid >> 4;
    int row0 = by * 64, col0 = bx * 64;
    int side = col0 >> 8;
    int wcol0 = col0 & 255;
    const float* Wbase = W1 + side * 768 * 256;
    u64 acc2[4][2];
#pragma unroll
    for (int i = 0; i < 4; i++) { acc2[i][0] = 0ull; acc2[i][1] = 0ull; }
    int ar = tid >> 2, ak = (tid & 3) * 4;
    int bk = tid >> 4, bn = (tid & 15) * 4;
    float4 av = *(const float4*)(g_emb + (row0 + ar) * 768 + ak);
    float4 bv = *(const float4*)(Wbase + bk * 256 + wcol0 + bn);
    for (int k0 = 0; k0 < 768; k0 += 16) {
        __syncthreads();
        *(float4*)&As[ar][ak] = av;
        *(float4*)&Bs[bk][bn] = bv;
        __syncthreads();
        if (k0 + 16 < 768) {
            av = *(const float4*)(g_emb + (row0 + ar) * 768 + k0 + 16 + ak);
            bv = *(const float4*)(Wbase + (k0 + 16 + bk) * 256 + wcol0 + bn);
        }
#pragma unroll
        for (int kk = 0; kk < 16; kk++) {
            float4 bv4 = *(const float4*)&Bs[kk][tx * 4];
            u64 b0 = ((u64*)&bv4)[0], b1 = ((u64*)&bv4)[1];
#pragma unroll
            for (int ii = 0; ii < 4; ii++) {
                u64 as = splat2(As[ty * 4 + ii][kk]);
                acc2[ii][0] = fma2(as, b0, acc2[ii][0]);
                acc2[ii][1] = fma2(as, b1, acc2[ii][1]);
            }
        }
    }
    float badd0 = 0.f, badd1 = 0.f, badd2 = 0.f, badd3 = 0.f;
    if (side) {
        const float* bp = bl1 + wcol0 + tx * 4;
        badd0 = bp[0]; badd1 = bp[1]; badd2 = bp[2]; badd3 = bp[3];
    }
#pragma unroll
    for (int ii = 0; ii < 4; ii++) {
        float o0, o1, o2, o3;
        unpack2(acc2[ii][0], o0, o1);
        unpack2(acc2[ii][1], o2, o3);
        float4 o = make_float4(o0 + badd0, o1 + badd1, o2 + badd2, o3 + badd3);
        *(float4*)(g_AB + (size_t)(row0 + ty * 4 + ii) * 512 + col0 + tx * 4) = o;
    }
}

// ---------------- K9: cross dots (32x64 tiles, 128 blocks) + row stats ----------
__global__ void k_dots() {
    __shared__ float As[32][16];
    __shared__ float Cs[64][17];
    __shared__ float sAs[32], qAs[32], sCs[64], qCs[64];
    int bxj = blockIdx.x, byi = blockIdx.y, b = blockIdx.z;
    int tid = threadIdx.x;
    int tx = tid & 15, ty = tid >> 4;
    const float* base = g_AB + (size_t)b * 131072;
    u64 acc2[2][2];
    acc2[0][0] = acc2[0][1] = acc2[1][0] = acc2[1][1] = 0ull;
    int rr = tid >> 2, rk = (tid & 3) * 4;
    bool hasA = tid < 128;
    float sA = 0.f, qA = 0.f, sC = 0.f, qC = 0.f;
    float4 av = make_float4(0.f, 0.f, 0.f, 0.f);
    if (hasA) av = *(const float4*)(base + (byi * 32 + rr) * 512 + rk);
    float4 cv = *(const float4*)(base + (bxj * 64 + rr) * 512 + 256 + rk);
    for (int k0 = 0; k0 < 256; k0 += 16) {
        if (hasA) {
            sA += (av.x + av.y) + (av.z + av.w);
            qA = fmaf(av.x, av.x, qA); qA = fmaf(av.y, av.y, qA);
            qA = fmaf(av.z, av.z, qA); qA = fmaf(av.w, av.w, qA);
        }
        sC += (cv.x + cv.y) + (cv.z + cv.w);
        qC = fmaf(cv.x, cv.x, qC); qC = fmaf(cv.y, cv.y, qC);
        qC = fmaf(cv.z, cv.z, qC); qC = fmaf(cv.w, cv.w, qC);
        __syncthreads();
        if (hasA) *(float4*)&As[rr][rk] = av;
        Cs[rr][rk] = cv.x; Cs[rr][rk + 1] = cv.y; Cs[rr][rk + 2] = cv.z; Cs[rr][rk + 3] = cv.w;
        __syncthreads();
        if (k0 + 16 < 256) {
            if (hasA) av = *(const float4*)(base + (byi * 32 + rr) * 512 + k0 + 16 + rk);
            cv = *(const float4*)(base + (bxj * 64 + rr) * 512 + 256 + k0 + 16 + rk);
        }
#pragma unroll
        for (int kk = 0; kk < 16; kk++) {
            u64 c0 = pack2(Cs[tx * 4 + 0][kk], Cs[tx * 4 + 1][kk]);
            u64 c1 = pack2(Cs[tx * 4 + 2][kk], Cs[tx * 4 + 3][kk]);
#pragma unroll
            for (int ii = 0; ii < 2; ii++) {
                u64 as = splat2(As[ty * 2 + ii][kk]);
                acc2[ii][0] = fma2(as, c0, acc2[ii][0]);
                acc2[ii][1] = fma2(as, c1, acc2[ii][1]);
            }
        }
    }
    sA += __shfl_xor_sync(FULLMASK, sA, 1); sA += __shfl_xor_sync(FULLMASK, sA, 2);
    qA += __shfl_xor_sync(FULLMASK, qA, 1); qA += __shfl_xor_sync(FULLMASK, qA, 2);
    sC += __shfl_xor_sync(FULLMASK, sC, 1); sC += __shfl_xor_sync(FULLMASK, sC, 2);
    qC += __shfl_xor_sync(FULLMASK, qC, 1); qC += __shfl_xor_sync(FULLMASK, qC, 2);
    __syncthreads();
    if ((tid & 3) == 0) {
        if (hasA) { sAs[rr] = sA; qAs[rr] = qA; }
        sCs[rr] = sC; qCs[rr] = qC;
    }
    __syncthreads();
    int ib = byi * 32 + ty * 2, jb = bxj * 64 + tx * 4;
#pragma unroll
    for (int ii = 0; ii < 2; ii++) {
        float D0, D1, D2, D3;
        unpack2(acc2[ii][0], D0, D1);
        unpack2(acc2[ii][1], D2, D3);
        float D[4] = {D0, D1, D2, D3};
        float sa = sAs[ty * 2 + ii], qa = qAs[ty * 2 + ii];
#pragma unroll
        for (int jj = 0; jj < 4; jj++) {
            float mean = (sa + sCs[tx * 4 + jj]) * (1.f / 256.f);
            float q = qa + qCs[tx * 4 + jj] + 2.f * D[jj];
            float var = q * (1.f / 256.f) - mean * mean;
            float rstd = rsqrtf(var + 1e-5f);
            g_mr[(size_t)(b * 256 + ib + ii) * 256 + jb + jj] = make_float2(rstd, -mean * rstd);
        }
    }
}

// ---------------- K10: fused add + LN(stats) + packed GELU + [256,8] proj ----------
// grid (256 i, 8 = b*2 + jhalf); 4 warps x 32 j each. Wc pre-scaled by 0.5
// (gelu2x returns 2*gelu).
__global__ void k_fused(
        const float* __restrict__ g1, const float* __restrict__ be1,
        const float* __restrict__ Wc, const float* __restrict__ bc,
        const float* __restrict__ Wc1, const float* __restrict__ bc1,
        const float* __restrict__ masks, float* __restrict__ out) {
    int b = blockIdx.y >> 1;
    int jhalf = blockIdx.y & 1;
    int i = blockIdx.x;
    int w = threadIdx.x >> 5, lane = threadIdx.x & 31;
    int j0 = jhalf * 128 + w * 32;

    const float* Arow = g_AB + (size_t)(b * 256 + i) * 512;
    float4 A1 = ((const float4*)Arow)[lane];
    float4 A2 = ((const float4*)Arow)[32 + lane];
    u64 a0p[4] = {((u64*)&A1)[0], ((u64*)&A1)[1], ((u64*)&A2)[0], ((u64*)&A2)[1]};
    float4 G1 = ((const float4*)g1)[lane], G2 = ((const float4*)g1)[32 + lane];
    float4 B1 = ((const float4*)be1)[lane], B2 = ((const float4*)be1)[32 + lane];
    u64 ggp[4] = {((u64*)&G1)[0], ((u64*)&G1)[1], ((u64*)&G2)[0], ((u64*)&G2)[1]};
    u64 bbp[4] = {((u64*)&B1)[0], ((u64*)&B1)[1], ((u64*)&B2)[0], ((u64*)&B2)[1]};

    u64 wcp[4][8];
#pragma unroll
    for (int p = 0; p < 4; p++) {
        int k0 = (p < 2) ? (lane * 4 + p * 2) : (128 + lane * 4 + (p - 2) * 2);
        int k1 = k0 + 1;
#pragma unroll
        for (int c = 0; c < 6; c++)
            wcp[p][c] = pack2(0.5f * Wc[k0 * 6 + c], 0.5f * Wc[k1 * 6 + c]);
        wcp[p][6] = pack2(0.5f * Wc1[k0 * 2], 0.5f * Wc1[k1 * 2]);
        wcp[p][7] = pack2(0.5f * Wc1[k0 * 2 + 1], 0.5f * Wc1[k1 * 2 + 1]);
    }
    int ch = ((lane & 1) << 2) | (lane & 2) | ((lane >> 2) & 1);
    float myb = (ch < 6) ? bc[ch] : bc1[ch - 6];

    const float* Bbase = g_AB + (size_t)b * 131072 + 256;
    const float2* mrp = g_mr + (size_t)(b * 256 + i) * 256 + j0;
    const float* mrow = masks + (b * 256 + i) * 256;
    float* outp = out + (size_t)((b * 256 + i) * 256) * 8;

    const ulonglong2* Bv = (const ulonglong2*)(Bbase + (size_t)j0 * 512);
    ulonglong2 U = Bv[lane], V = Bv[32 + lane];
    float2 mr = mrp[0];

    for (int jj = 0; jj < 32; jj++) {
        int j = j0 + jj;
        u64 xs[4];
        xs[0] = add2(a0p[0], U.x); xs[1] = add2(a0p[1], U.y);
        xs[2] = add2(a0p[2], V.x); xs[3] = add2(a0p[3], V.y);
        u64 r2 = splat2(mr.x);       // rstd
        u64 nm2 = splat2(mr.y);      // -mean*rstd
        if (jj + 1 < 32) {           // prefetch next B row + stats
            const ulonglong2* Bn = (const ulonglong2*)(Bbase + (size_t)(j + 1) * 512);
            U = Bn[lane]; V = Bn[32 + lane];
            mr = mrp[jj + 1];
        }
        u64 ge[4];
#pragma unroll
        for (int p = 0; p < 4; p++) {
            u64 rg = mul2(ggp[p], r2);
            u64 c2 = fma2(nm2, ggp[p], bbp[p]);
            u64 y2 = fma2(xs[p], rg, c2);
            ge[p] = gelu2x(y2);
        }
        u64 acc2[8];
#pragma unroll
        for (int c = 0; c < 8; c++) {
            u64 a = mul2(ge[0], wcp[0][c]);
            a = fma2(ge[1], wcp[1][c], a);
            a = fma2(ge[2], wcp[2][c], a);
            acc2[c] = fma2(ge[3], wcp[3][c], a);
        }
        float acc[8];
#pragma unroll
        for (int c = 0; c < 8; c++) { float ua, ub; unpack2(acc2[c], ua, ub); acc[c] = ua + ub; }
#pragma unroll
        for (int c = 0; c < 4; c++) {
            float keep = (lane & 1) ? acc[c + 4] : acc[c];
            float send = (lane & 1) ? acc[c] : acc[c + 4];
            acc[c] = keep + __shfl_xor_sync(FULLMASK, send, 1);
        }
#pragma unroll
        for (int c = 0; c < 2; c++) {
            float keep = (lane & 2) ? acc[c + 2] : acc[c];
            float send = (lane & 2) ? acc[c] : acc[c + 2];
            acc[c] = keep + __shfl_xor_sync(FULLMASK, send, 2);
        }
        {
            float keep = (lane & 4) ? acc[1] : acc[0];
            float send = (lane & 4) ? acc[0] : acc[1];
            acc[0] = keep + __shfl_xor_sync(FULLMASK, send, 4);
        }
        acc[0] += __shfl_xor_sync(FULLMASK, acc[0], 8);
        acc[0] += __shfl_xor_sync(FULLMASK, acc[0], 16);

        float mval = mrow[j];
        if (lane < 8) outp[j * 8 + ch] = (acc[0] + myb) * mval;
    }
}

extern "C" void kernel_launch(void* const* d_in, const int* in_sizes, int n_in,
                              void* d_out, int out_size) {
    const float* embeddings = (const float*)d_in[0];
    const float* masks      = (const float*)d_in[1];
    const int* asp_st = (const int*)d_in[2];
    const int* asp_ed = (const int*)d_in[3];
    const int* opi_st = (const int*)d_in[4];
    const int* opi_ed = (const int*)d_in[5];
    const int* sent_id = (const int*)d_in[6];
    const float* edge_embed = (const float*)d_in[7];
    const float* W_tp = (const float*)d_in[8];
    const float* b_tp = (const float*)d_in[9];
    const float* W_attn = (const float*)d_in[10];
    const float* b_attn = (const float*)d_in[11];
    const float* W_gat = (const float*)d_in[12];
    const float* b_gat = (const float*)d_in[13];
    const float* gamma0 = (const float*)d_in[14];
    const float* beta0 = (const float*)d_in[15];
    const float* W1 = (const float*)d_in[16];
    const float* bl1 = (const float*)d_in[17];
    const float* gamma1 = (const float*)d_in[18];
    const float* beta1 = (const float*)d_in[19];
    const float* Wc = (const float*)d_in[20];
    const float* bc = (const float*)d_in[21];
    const float* Wc1 = (const float*)d_in[22];
    const float* bc1 = (const float*)d_in[23];
    float* out = (float*)d_out;

    k_ln0<<<1024, 256>>>(embeddings, gamma0, beta0);
    k_spans<<<64, 256>>>(asp_st, asp_ed, opi_st, opi_ed, sent_id);
    k_gemm_small<<<192, 256>>>(0, 1539, W_tp, b_tp, 0);
    k_tdots<<<dim3(16, 4), 128>>>(edge_embed, W_attn);
    k_agg<<<dim3(4, 6), 128>>>(asp_st, asp_ed, opi_st, opi_ed, edge_embed, b_attn);
    k_gemm_small<<<192, 256>>>(1, 1536, W_gat, b_gat, 1);
    k_scatter<<<dim3(4, 6), 128>>>(asp_st, opi_st);
    k_gemm<<<dim3(8, 16), 256>>>(W1, bl1);
    k_dots<<<dim3(4, 8, 4), 256>>>();
    k_fused<<<dim3(256, 8), 128>>>(gamma1, beta1, Wc, bc, Wc1, bc1, masks, out);
}